// round 1
// baseline (speedup 1.0000x reference)
#include <cuda_runtime.h>
#include <cuda_bf16.h>
#include <math.h>

#define TT 512
#define BB 32
#define DD 768
#define HH 256
#define GG 1024   // 4*H
#define KK 32
#define NBLK 128  // recurrence persistent blocks

// ---------------- device scratch ----------------
__device__ float d_pre[(size_t)2 * TT * BB * GG];      // [dir][t][b][4H]  134MB
__device__ float d_hall[(size_t)2 * TT * BB * HH];     // [dir][t][b][H]   33.5MB
__device__ float d_hbuf[2 * 2 * BB * HH];              // [parity][dir][b][H]
__device__ float d_em[(size_t)BB * TT * KK];           // [b][t][k]
__device__ unsigned char d_hist[(size_t)BB * 511 * KK];
__device__ float d_nll[BB];
__device__ int d_last[BB];
__device__ unsigned d_barc = 0, d_barg = 0;

// ---------------- K1: pre = x @ W_ih^T + b  (both dirs, bwd gathers reversed rows)
__global__ void __launch_bounds__(256) k_pre_gemm(
    const float* __restrict__ x, const int* __restrict__ lengths,
    const float* __restrict__ Wf, const float* __restrict__ bf_,
    const float* __restrict__ Wb, const float* __restrict__ bb_)
{
    const int dir = blockIdx.z;
    const float* __restrict__ W = dir ? Wb : Wf;
    const float* __restrict__ bias = dir ? bb_ : bf_;
    const int m0 = blockIdx.x * 64;
    const int n0 = blockIdx.y * 64;
    __shared__ float As[16][68];
    __shared__ float Bs[16][68];
    const int tid = threadIdx.x;
    const int lrow = tid >> 2;            // 0..63
    const int kq = (tid & 3) * 4;         // 0,4,8,12
    {
        // precompute row pointers
    }
    int r = m0 + lrow;
    int t = r >> 5, b = r & 31;
    int st = t;
    if (dir) { int L = lengths[b]; st = (t < L) ? (L - 1 - t) : t; }
    const float4* arow = reinterpret_cast<const float4*>(x + ((size_t)b * TT + st) * DD);
    const float4* brow = reinterpret_cast<const float4*>(W + (size_t)(n0 + lrow) * DD);
    const int ty = tid >> 4, tx = tid & 15;
    float acc[4][4];
#pragma unroll
    for (int i = 0; i < 4; i++)
#pragma unroll
        for (int j = 0; j < 4; j++) acc[i][j] = 0.f;

    for (int k0 = 0; k0 < DD; k0 += 16) {
        float4 av = arow[(k0 + kq) >> 2];
        float4 bv = brow[(k0 + kq) >> 2];
        __syncthreads();
        As[kq + 0][lrow] = av.x; As[kq + 1][lrow] = av.y;
        As[kq + 2][lrow] = av.z; As[kq + 3][lrow] = av.w;
        Bs[kq + 0][lrow] = bv.x; Bs[kq + 1][lrow] = bv.y;
        Bs[kq + 2][lrow] = bv.z; Bs[kq + 3][lrow] = bv.w;
        __syncthreads();
#pragma unroll
        for (int kk = 0; kk < 16; kk++) {
            float4 a4 = *reinterpret_cast<const float4*>(&As[kk][ty * 4]);
            float4 b4 = *reinterpret_cast<const float4*>(&Bs[kk][tx * 4]);
            acc[0][0] = fmaf(a4.x, b4.x, acc[0][0]);
            acc[0][1] = fmaf(a4.x, b4.y, acc[0][1]);
            acc[0][2] = fmaf(a4.x, b4.z, acc[0][2]);
            acc[0][3] = fmaf(a4.x, b4.w, acc[0][3]);
            acc[1][0] = fmaf(a4.y, b4.x, acc[1][0]);
            acc[1][1] = fmaf(a4.y, b4.y, acc[1][1]);
            acc[1][2] = fmaf(a4.y, b4.z, acc[1][2]);
            acc[1][3] = fmaf(a4.y, b4.w, acc[1][3]);
            acc[2][0] = fmaf(a4.z, b4.x, acc[2][0]);
            acc[2][1] = fmaf(a4.z, b4.y, acc[2][1]);
            acc[2][2] = fmaf(a4.z, b4.z, acc[2][2]);
            acc[2][3] = fmaf(a4.z, b4.w, acc[2][3]);
            acc[3][0] = fmaf(a4.w, b4.x, acc[3][0]);
            acc[3][1] = fmaf(a4.w, b4.y, acc[3][1]);
            acc[3][2] = fmaf(a4.w, b4.z, acc[3][2]);
            acc[3][3] = fmaf(a4.w, b4.w, acc[3][3]);
        }
    }
#pragma unroll
    for (int i = 0; i < 4; i++) {
        int rr = m0 + ty * 4 + i;
        int t2 = rr >> 5, b2 = rr & 31;
        size_t base = (((size_t)dir * TT + t2) * BB + b2) * GG;
#pragma unroll
        for (int j = 0; j < 4; j++) {
            int n = n0 + tx * 4 + j;
            d_pre[base + n] = acc[i][j] + __ldg(&bias[n]);
        }
    }
}

// ---------------- grid barrier (all NBLK blocks resident) ----------------
__device__ __forceinline__ void grid_barrier()
{
    __syncthreads();
    if (threadIdx.x == 0) {
        volatile unsigned* vg = &d_barg;
        unsigned gen = *vg;
        __threadfence();
        unsigned t = atomicAdd(&d_barc, 1u);
        if (t == NBLK - 1) {
            atomicExch(&d_barc, 0u);
            __threadfence();
            atomicAdd(&d_barg, 1u);
        } else {
            while (*vg == gen) { }
        }
    }
    __syncthreads();
}

__device__ __forceinline__ float sigmoidf_(float v) { return 1.f / (1.f + __expf(-v)); }

// ---------------- K2: LSTM recurrence (persistent, W_hh register-cached) ----
__global__ void __launch_bounds__(256, 1) k_lstm(
    const float* __restrict__ Whf, const float* __restrict__ Whb)
{
    const int bid = blockIdx.x;
    const int dir = bid >> 6;
    const int rem = bid & 63;
    const int jc = rem >> 2;        // 0..15 : j chunk of 16
    const int bg = rem & 3;         // 0..3  : batch group of 8
    const float* __restrict__ Whh = dir ? Whb : Whf;
    const int tid = threadIdx.x;
    const int kc = tid >> 4;        // 0..15 : k chunk of 16
    const int rg = tid & 15;        // jj within chunk
    const int jg = jc * 16 + rg;

    // register-resident W_hh slice: 4 gates x 16 k
    float w0[16], w1[16], w2[16], w3[16];
#pragma unroll
    for (int kk = 0; kk < 16; kk++) {
        int k = kc * 16 + kk;
        w0[kk] = Whh[(size_t)(0 * HH + jg) * HH + k];
        w1[kk] = Whh[(size_t)(1 * HH + jg) * HH + k];
        w2[kk] = Whh[(size_t)(2 * HH + jg) * HH + k];
        w3[kk] = Whh[(size_t)(3 * HH + jg) * HH + k];
    }

    __shared__ float h_s[8][256];
    __shared__ float part[256][33];
    __shared__ float c_s[8][16];

    if (tid < 128) c_s[tid >> 4][tid & 15] = 0.f;
    for (int i = tid; i < 8 * 256; i += 256) {
        int b = i >> 8, j = i & 255;
        d_hbuf[((0 * 2 + dir) * BB + bg * 8 + b) * HH + j] = 0.f;
    }
    __threadfence();
    grid_barrier();

    for (int t = 0; t < TT; t++) {
        const int par = t & 1;
        float p0 = 0.f, p1 = 0.f, p2 = 0.f, p3 = 0.f;
        if (tid < 128) {   // prefetch pre early (hides DRAM latency behind FFMAs)
            int b = bg * 8 + (tid >> 4);
            int j = jc * 16 + (tid & 15);
            size_t base = (((size_t)dir * TT + t) * BB + b) * GG;
            p0 = __ldg(&d_pre[base + 0 * HH + j]);
            p1 = __ldg(&d_pre[base + 1 * HH + j]);
            p2 = __ldg(&d_pre[base + 2 * HH + j]);
            p3 = __ldg(&d_pre[base + 3 * HH + j]);
        }
        for (int i = tid; i < 8 * 256; i += 256) {
            int b = i >> 8, j = i & 255;
            h_s[b][j] = __ldcg(&d_hbuf[((par * 2 + dir) * BB + bg * 8 + b) * HH + j]);
        }
        __syncthreads();

        float a0[8], a1[8], a2[8], a3[8];
#pragma unroll
        for (int b = 0; b < 8; b++) { a0[b] = 0.f; a1[b] = 0.f; a2[b] = 0.f; a3[b] = 0.f; }
#pragma unroll
        for (int kk = 0; kk < 16; kk++) {
            int k = kc * 16 + kk;
#pragma unroll
            for (int b = 0; b < 8; b++) {
                float hv = h_s[b][k];   // broadcast within half-warp
                a0[b] = fmaf(hv, w0[kk], a0[b]);
                a1[b] = fmaf(hv, w1[kk], a1[b]);
                a2[b] = fmaf(hv, w2[kk], a2[b]);
                a3[b] = fmaf(hv, w3[kk], a3[b]);
            }
        }
#pragma unroll
        for (int b = 0; b < 8; b++) {
            part[tid][b * 4 + 0] = a0[b];
            part[tid][b * 4 + 1] = a1[b];
            part[tid][b * 4 + 2] = a2[b];
            part[tid][b * 4 + 3] = a3[b];
        }
        __syncthreads();

        if (tid < 128) {
            int b = tid >> 4, lj = tid & 15;
            float g0 = 0.f, g1 = 0.f, g2 = 0.f, g3 = 0.f;
#pragma unroll
            for (int kk2 = 0; kk2 < 16; kk2++) {
                const float* p = &part[kk2 * 16 + lj][b * 4];
                g0 += p[0]; g1 += p[1]; g2 += p[2]; g3 += p[3];
            }
            g0 += p0; g1 += p1; g2 += p2; g3 += p3;
            float iv = sigmoidf_(g0);
            float fv = sigmoidf_(g1);
            float gv = tanhf(g2);
            float ov = sigmoidf_(g3);
            float c = fv * c_s[b][lj] + iv * gv;
            c_s[b][lj] = c;
            float h = ov * tanhf(c);
            int gb = bg * 8 + b;
            int j = jc * 16 + lj;
            __stcg(&d_hbuf[(((par ^ 1) * 2 + dir) * BB + gb) * HH + j], h);
            d_hall[(((size_t)dir * TT + t) * BB + gb) * HH + j] = h;
        }
        __threadfence();
        grid_barrier();
    }
}

// ---------------- K3: emissions = [h_f ; h_b(un-reversed)] @ W_clf^T + b_clf
__global__ void __launch_bounds__(512) k_emis(
    const int* __restrict__ lengths,
    const float* __restrict__ Wclf, const float* __restrict__ bclf)
{
    __shared__ float hs[16 * 513];
    const int b = blockIdx.y;
    const int t0 = blockIdx.x * 16;
    const int tid = threadIdx.x;
    const int L = lengths[b];
    for (int i = tid; i < 16 * 512; i += 512) {
        int row = i >> 9, col = i & 511;
        int t = t0 + row;
        float v;
        if (col < 256) {
            v = d_hall[(((size_t)0 * TT + t) * BB + b) * HH + col];
        } else {
            int st = (t < L) ? (L - 1 - t) : t;
            v = d_hall[(((size_t)1 * TT + st) * BB + b) * HH + (col - 256)];
        }
        hs[row * 513 + col] = v;
    }
    __syncthreads();
    const int k = tid >> 4;    // 0..31
    const int tt = tid & 15;   // 0..15
    float acc = __ldg(&bclf[k]);
    const float* hrow = &hs[tt * 513];
    const float* wrow = &Wclf[(size_t)k * 512];
#pragma unroll 8
    for (int j = 0; j < 512; j++) acc = fmaf(hrow[j], __ldg(&wrow[j]), acc);
    d_em[((size_t)b * TT + t0 + tt) * KK + k] = acc;
}

// ---------------- warp helpers ----------------
__device__ __forceinline__ float wmaxf(float v) {
#pragma unroll
    for (int o = 16; o; o >>= 1) v = fmaxf(v, __shfl_xor_sync(0xffffffffu, v, o));
    return v;
}
__device__ __forceinline__ float wsumf(float v) {
#pragma unroll
    for (int o = 16; o; o >>= 1) v += __shfl_xor_sync(0xffffffffu, v, o);
    return v;
}

// ---------------- K4: fused CRF forward (logZ, numerator) + Viterbi forward
__global__ void __launch_bounds__(1024) k_crf(
    const int* __restrict__ lengths, const int* __restrict__ targets,
    const float* __restrict__ st, const float* __restrict__ en,
    const float* __restrict__ trans)
{
    const int b = blockIdx.x;
    const int tid = threadIdx.x;
    const int j = tid >> 5, i = tid & 31;
    __shared__ float tr_s[32][32];      // tr_s[j][i] = trans[i][j]
    __shared__ float alpha[32], score[32], alpha_n[32], score_n[32];
    tr_s[j][i] = trans[i * 32 + j];
    if (tid < 32) {
        float e = d_em[((size_t)b * TT + 0) * KK + tid];
        alpha[tid] = st[tid] + e;
        score[tid] = st[tid] + e;
    }
    __syncthreads();
    const int L = lengths[b];
    const float base = tr_s[j][i];
    for (int t = 1; t < L; t++) {
        float em_tj = __ldg(&d_em[((size_t)b * TT + t) * KK + j]);
        // CRF forward (logsumexp over previous tag i)
        float v = alpha[i] + base;
        float m = wmaxf(v);
        float s = wsumf(__expf(v - m));
        // Viterbi (max/argmax, first-index tie-break)
        float bm = score[i] + base;
        int bi = i;
#pragma unroll
        for (int o = 16; o; o >>= 1) {
            float om = __shfl_xor_sync(0xffffffffu, bm, o);
            int oi = __shfl_xor_sync(0xffffffffu, bi, o);
            if (om > bm || (om == bm && oi < bi)) { bm = om; bi = oi; }
        }
        if (i == 0) {
            alpha_n[j] = m + __logf(s) + em_tj;
            score_n[j] = bm + em_tj;
            d_hist[((size_t)b * 511 + (t - 1)) * KK + j] = (unsigned char)bi;
        }
        __syncthreads();
        if (tid < 32) { alpha[tid] = alpha_n[tid]; score[tid] = score_n[tid]; }
        __syncthreads();
    }
    if (j == 0) {
        float a = alpha[i] + en[i];
        float m = wmaxf(a);
        float s = wsumf(__expf(a - m));
        float logZ = m + __logf(s);
        float bm = score[i] + en[i];
        int bi = i;
#pragma unroll
        for (int o = 16; o; o >>= 1) {
            float om = __shfl_xor_sync(0xffffffffu, bm, o);
            int oi = __shfl_xor_sync(0xffffffffu, bi, o);
            if (om > bm || (om == bm && oi < bi)) { bm = om; bi = oi; }
        }
        // numerator, lane-parallel over t
        float np = 0.f;
        for (int t = 1 + i; t < L; t += 32) {
            int pt = targets[b * TT + t - 1];
            int ct = targets[b * TT + t];
            np += trans[pt * 32 + ct] + d_em[((size_t)b * TT + t) * KK + ct];
        }
        np = wsumf(np);
        if (i == 0) {
            int tg0 = targets[b * TT + 0];
            int tgl = targets[b * TT + L - 1];
            float num = st[tg0] + d_em[((size_t)b * TT) * KK + tg0] + np + en[tgl];
            d_nll[b] = num - logZ;
            d_last[b] = bi;
        }
    }
}

// ---------------- K5: Viterbi backtrack + loss write ----------------
__global__ void k_back(const int* __restrict__ lengths, float* __restrict__ out, int out_size)
{
    const int b = threadIdx.x;
    const bool has_loss = (out_size >= BB * TT + 1);
    const int off = has_loss ? 1 : 0;
    if (b < BB && out_size >= BB * TT) {
        int L = lengths[b];
        int tag = d_last[b];
        out[off + b * TT + (TT - 1)] = ((TT - 1) < L) ? (float)tag : 0.f;
        for (int s = TT - 2; s >= 0; s--) {
            int t = s + 1;
            int prev = (t < L) ? (int)d_hist[((size_t)b * 511 + s) * KK + tag] : tag;
            out[off + b * TT + s] = (s < L) ? (float)prev : 0.f;
            tag = prev;
        }
    }
    __syncthreads();
    if (b == 0 && (has_loss || out_size == 1)) {
        float acc = 0.f;
        for (int q = 0; q < BB; q++) acc += d_nll[q];
        out[0] = -acc / (float)BB;
    }
}

// ---------------- launch ----------------
extern "C" void kernel_launch(void* const* d_in, const int* in_sizes, int n_in,
                              void* d_out, int out_size)
{
    const float* x      = (const float*)d_in[0];
    const int* lengths  = (const int*)d_in[1];
    // d_in[2] = mask (recomputed from lengths, ignored)
    const int* targets  = (const int*)d_in[3];
    const float* Wihf   = (const float*)d_in[4];
    const float* Whhf   = (const float*)d_in[5];
    const float* bf_    = (const float*)d_in[6];
    const float* Wihb   = (const float*)d_in[7];
    const float* Whhb   = (const float*)d_in[8];
    const float* bb_    = (const float*)d_in[9];
    const float* Wclf   = (const float*)d_in[10];
    const float* bclf   = (const float*)d_in[11];
    const float* st     = (const float*)d_in[12];
    const float* en     = (const float*)d_in[13];
    const float* tr     = (const float*)d_in[14];

    k_pre_gemm<<<dim3(256, 16, 2), 256>>>(x, lengths, Wihf, bf_, Wihb, bb_);
    k_lstm<<<NBLK, 256>>>(Whhf, Whhb);
    k_emis<<<dim3(32, 32), 512>>>(lengths, Wclf, bclf);
    k_crf<<<32, 1024>>>(lengths, targets, st, en, tr);
    k_back<<<1, 32>>>(lengths, (float*)d_out, out_size);
}

// round 2
// speedup vs baseline: 1.3162x; 1.3162x over previous
#include <cuda_runtime.h>
#include <cuda_bf16.h>
#include <math.h>

#define TT 512
#define BB 32
#define DD 768
#define HH 256
#define GG 1024   // 4*H
#define KK 32
#define NBLK 128  // recurrence persistent blocks

typedef unsigned long long ull;

// ---------------- packed f32x2 helpers (sm_103a FFMA2) ----------------
__device__ __forceinline__ ull pack2(float x, float y) {
    ull r; asm("mov.b64 %0,{%1,%2};" : "=l"(r) : "f"(x), "f"(y)); return r;
}
__device__ __forceinline__ void unpack2(ull v, float& x, float& y) {
    asm("mov.b64 {%0,%1},%2;" : "=f"(x), "=f"(y) : "l"(v));
}
__device__ __forceinline__ ull ffma2(ull a, ull b, ull c) {
    ull d; asm("fma.rn.f32x2 %0,%1,%2,%3;" : "=l"(d) : "l"(a), "l"(b), "l"(c)); return d;
}

// ---------------- device scratch ----------------
__device__ float d_pre[(size_t)2 * TT * BB * GG];      // [dir][t][b][4H]
__device__ float d_hall[(size_t)2 * TT * BB * HH];     // [dir][t][b][H]
__device__ float d_hbuf[2 * 2 * BB * HH];              // [parity][dir][b][H]
__device__ float d_em[(size_t)BB * TT * KK];           // [b][t][k]
__device__ unsigned char d_hist[(size_t)BB * 511 * KK];
__device__ float d_nll[BB];
__device__ int d_last[BB];
__device__ unsigned d_barc = 0, d_barg = 0;

// ============ K1: pre = x @ W_ih^T + b (128x64 tile, FFMA2, dbl-buffer) ====
__global__ void __launch_bounds__(256) k_pre_gemm(
    const float* __restrict__ x, const int* __restrict__ lengths,
    const float* __restrict__ Wf, const float* __restrict__ bf_,
    const float* __restrict__ Wb, const float* __restrict__ bb_)
{
    const int dir = blockIdx.z;
    const float* __restrict__ W = dir ? Wb : Wf;
    const float* __restrict__ bias = dir ? bb_ : bf_;
    const int m0 = blockIdx.x * 128;
    const int n0 = blockIdx.y * 64;
    __shared__ __align__(16) float As[2][16][128];
    __shared__ __align__(16) float Bs[2][16][64];
    const int tid = threadIdx.x;

    // loader roles
    const int rowA = tid >> 1;            // 0..127
    const int kqa  = (tid & 1) * 8;       // 0 or 8
    const int rowB = tid >> 2;            // 0..63
    const int kqb  = (tid & 3) * 4;       // 0,4,8,12
    int rA = m0 + rowA;
    int tA = rA >> 5, bA = rA & 31;
    int stA = tA;
    if (dir) { int L = __ldg(&lengths[bA]); stA = (tA < L) ? (L - 1 - tA) : tA; }
    const float4* aptr = reinterpret_cast<const float4*>(x + ((size_t)bA * TT + stA) * DD);
    const float4* bptr = reinterpret_cast<const float4*>(W + (size_t)(n0 + rowB) * DD);

    // compute roles
    const int ty = tid >> 3;              // 0..31 -> rows ty*4..+4
    const int tx = tid & 7;               // 0..7  -> cols tx*8..+8

    ull acc[4][4];
#pragma unroll
    for (int i = 0; i < 4; i++)
#pragma unroll
        for (int p = 0; p < 4; p++) acc[i][p] = 0ull;

    // preload chunk 0
    float4 a0 = aptr[(0 + kqa) >> 2];
    float4 a1 = aptr[(0 + kqa + 4) >> 2];
    float4 b0 = bptr[(0 + kqb) >> 2];
    {
        As[0][kqa + 0][rowA] = a0.x; As[0][kqa + 1][rowA] = a0.y;
        As[0][kqa + 2][rowA] = a0.z; As[0][kqa + 3][rowA] = a0.w;
        As[0][kqa + 4][rowA] = a1.x; As[0][kqa + 5][rowA] = a1.y;
        As[0][kqa + 6][rowA] = a1.z; As[0][kqa + 7][rowA] = a1.w;
        Bs[0][kqb + 0][rowB] = b0.x; Bs[0][kqb + 1][rowB] = b0.y;
        Bs[0][kqb + 2][rowB] = b0.z; Bs[0][kqb + 3][rowB] = b0.w;
    }
    __syncthreads();

    const int NCH = DD / 16;  // 48
    for (int c = 0; c < NCH; c++) {
        const int cb = c & 1;
        if (c + 1 < NCH) {
            int k0 = (c + 1) * 16;
            a0 = aptr[(k0 + kqa) >> 2];
            a1 = aptr[(k0 + kqa + 4) >> 2];
            b0 = bptr[(k0 + kqb) >> 2];
        }
#pragma unroll
        for (int kk = 0; kk < 16; kk++) {
            float4 a4 = *reinterpret_cast<const float4*>(&As[cb][kk][ty * 4]);
            ull bp0 = *reinterpret_cast<const ull*>(&Bs[cb][kk][tx * 8 + 0]);
            ull bp1 = *reinterpret_cast<const ull*>(&Bs[cb][kk][tx * 8 + 2]);
            ull bp2 = *reinterpret_cast<const ull*>(&Bs[cb][kk][tx * 8 + 4]);
            ull bp3 = *reinterpret_cast<const ull*>(&Bs[cb][kk][tx * 8 + 6]);
            ull ad;
            ad = pack2(a4.x, a4.x);
            acc[0][0] = ffma2(ad, bp0, acc[0][0]);
            acc[0][1] = ffma2(ad, bp1, acc[0][1]);
            acc[0][2] = ffma2(ad, bp2, acc[0][2]);
            acc[0][3] = ffma2(ad, bp3, acc[0][3]);
            ad = pack2(a4.y, a4.y);
            acc[1][0] = ffma2(ad, bp0, acc[1][0]);
            acc[1][1] = ffma2(ad, bp1, acc[1][1]);
            acc[1][2] = ffma2(ad, bp2, acc[1][2]);
            acc[1][3] = ffma2(ad, bp3, acc[1][3]);
            ad = pack2(a4.z, a4.z);
            acc[2][0] = ffma2(ad, bp0, acc[2][0]);
            acc[2][1] = ffma2(ad, bp1, acc[2][1]);
            acc[2][2] = ffma2(ad, bp2, acc[2][2]);
            acc[2][3] = ffma2(ad, bp3, acc[2][3]);
            ad = pack2(a4.w, a4.w);
            acc[3][0] = ffma2(ad, bp0, acc[3][0]);
            acc[3][1] = ffma2(ad, bp1, acc[3][1]);
            acc[3][2] = ffma2(ad, bp2, acc[3][2]);
            acc[3][3] = ffma2(ad, bp3, acc[3][3]);
        }
        if (c + 1 < NCH) {
            const int nb = (c + 1) & 1;
            As[nb][kqa + 0][rowA] = a0.x; As[nb][kqa + 1][rowA] = a0.y;
            As[nb][kqa + 2][rowA] = a0.z; As[nb][kqa + 3][rowA] = a0.w;
            As[nb][kqa + 4][rowA] = a1.x; As[nb][kqa + 5][rowA] = a1.y;
            As[nb][kqa + 6][rowA] = a1.z; As[nb][kqa + 7][rowA] = a1.w;
            Bs[nb][kqb + 0][rowB] = b0.x; Bs[nb][kqb + 1][rowB] = b0.y;
            Bs[nb][kqb + 2][rowB] = b0.z; Bs[nb][kqb + 3][rowB] = b0.w;
            __syncthreads();
        }
    }

#pragma unroll
    for (int i = 0; i < 4; i++) {
        int rr = m0 + ty * 4 + i;
        int t2 = rr >> 5, b2 = rr & 31;
        size_t base = (((size_t)dir * TT + t2) * BB + b2) * GG;
#pragma unroll
        for (int p = 0; p < 4; p++) {
            float lo, hi;
            unpack2(acc[i][p], lo, hi);
            int n = n0 + tx * 8 + p * 2;
            d_pre[base + n]     = lo + __ldg(&bias[n]);
            d_pre[base + n + 1] = hi + __ldg(&bias[n + 1]);
        }
    }
}

// ---------------- grid barrier (all NBLK blocks resident) ----------------
__device__ __forceinline__ void grid_barrier()
{
    __syncthreads();
    if (threadIdx.x == 0) {
        volatile unsigned* vg = &d_barg;
        unsigned gen = *vg;
        __threadfence();
        unsigned t = atomicAdd(&d_barc, 1u);
        if (t == NBLK - 1) {
            atomicExch(&d_barc, 0u);
            __threadfence();
            atomicAdd(&d_barg, 1u);
        } else {
            while (*vg == gen) { }
        }
    }
    __syncthreads();
}

__device__ __forceinline__ float sigmoidf_(float v) { return 1.f / (1.f + __expf(-v)); }

// ============ K2: LSTM recurrence (persistent, FFMA2, shfl reduce) =========
// block: (dir 2) x (jc 8 : 32 j) x (bg 8 : 4 batches) = 128 blocks
// thread: jj = tid>>3 (0..31), kc = tid&7; k = kk*8+kc (interleaved)
__global__ void __launch_bounds__(256, 1) k_lstm(
    const float* __restrict__ Whf, const float* __restrict__ Whb)
{
    const int bid = blockIdx.x;
    const int dir = bid >> 6;
    const int rem = bid & 63;
    const int jc = rem >> 3;
    const int bg = rem & 7;
    const float* __restrict__ Whh = dir ? Whb : Whf;
    const int tid = threadIdx.x;
    const int jj = tid >> 3;
    const int kc = tid & 7;
    const int j = jc * 32 + jj;

    // W slice in registers: w[g][kk], k = kk*8+kc
    float w[4][32];
#pragma unroll
    for (int g = 0; g < 4; g++)
#pragma unroll
        for (int kk = 0; kk < 32; kk++)
            w[g][kk] = __ldg(&Whh[(size_t)(g * HH + j) * HH + (kk * 8 + kc)]);

    __shared__ __align__(16) float h_s[2][HH][4];
    __shared__ float pre_s[2][512];

    float cst[4] = {0.f, 0.f, 0.f, 0.f};   // used on kc==0 lanes

    // zero initial h
    for (int q = 0; q < 4; q++) {
        int i = tid + q * 256;
        int b = i >> 8, k = i & 255;
        d_hbuf[((0 * 2 + dir) * BB + bg * 4 + b) * HH + k] = 0.f;
    }
    __threadfence();
    grid_barrier();

    for (int t = 0; t < TT; t++) {
        const int par = t & 1;
        // stage pre (2 per thread) and h (4 per thread)
        float pv0, pv1, hv[4];
        {
            size_t pbase = (((size_t)dir * TT + t) * BB + bg * 4) * GG;
            int i0 = tid, i1 = tid + 256;
            pv0 = __ldcg(&d_pre[pbase + (size_t)((i0 >> 5) & 3) * GG + (i0 >> 7) * HH + jc * 32 + (i0 & 31)]);
            pv1 = __ldcg(&d_pre[pbase + (size_t)((i1 >> 5) & 3) * GG + (i1 >> 7) * HH + jc * 32 + (i1 & 31)]);
        }
#pragma unroll
        for (int q = 0; q < 4; q++) {
            int i = tid + q * 256;
            int b = i >> 8, k = i & 255;
            hv[q] = __ldcg(&d_hbuf[((par * 2 + dir) * BB + bg * 4 + b) * HH + k]);
        }
        pre_s[par][tid] = pv0;
        pre_s[par][tid + 256] = pv1;
#pragma unroll
        for (int q = 0; q < 4; q++) {
            int i = tid + q * 256;
            h_s[par][i & 255][i >> 8] = hv[q];
        }
        __syncthreads();

        ull acc[4][2];
#pragma unroll
        for (int g = 0; g < 4; g++) { acc[g][0] = 0ull; acc[g][1] = 0ull; }
#pragma unroll
        for (int kk = 0; kk < 32; kk++) {
            int k = kk * 8 + kc;
            ull hp0 = *reinterpret_cast<const ull*>(&h_s[par][k][0]);
            ull hp1 = *reinterpret_cast<const ull*>(&h_s[par][k][2]);
#pragma unroll
            for (int g = 0; g < 4; g++) {
                ull wd = pack2(w[g][kk], w[g][kk]);
                acc[g][0] = ffma2(wd, hp0, acc[g][0]);
                acc[g][1] = ffma2(wd, hp1, acc[g][1]);
            }
        }
        // unpack to s[g][b] and reduce over the 8 kc lanes
        float s[4][4];
#pragma unroll
        for (int g = 0; g < 4; g++) {
            unpack2(acc[g][0], s[g][0], s[g][1]);
            unpack2(acc[g][1], s[g][2], s[g][3]);
        }
#pragma unroll
        for (int d = 1; d < 8; d <<= 1)
#pragma unroll
            for (int g = 0; g < 4; g++)
#pragma unroll
                for (int b = 0; b < 4; b++)
                    s[g][b] += __shfl_xor_sync(0xffffffffu, s[g][b], d);

        if (kc == 0) {
#pragma unroll
            for (int b = 0; b < 4; b++) {
                float gi = s[0][b] + pre_s[par][0 * 128 + b * 32 + jj];
                float gf = s[1][b] + pre_s[par][1 * 128 + b * 32 + jj];
                float gg = s[2][b] + pre_s[par][2 * 128 + b * 32 + jj];
                float go = s[3][b] + pre_s[par][3 * 128 + b * 32 + jj];
                float c = sigmoidf_(gf) * cst[b] + sigmoidf_(gi) * tanhf(gg);
                cst[b] = c;
                float h = sigmoidf_(go) * tanhf(c);
                int gb = bg * 4 + b;
                __stcg(&d_hbuf[(((par ^ 1) * 2 + dir) * BB + gb) * HH + j], h);
                d_hall[(((size_t)dir * TT + t) * BB + gb) * HH + j] = h;
            }
        }
        __threadfence();
        grid_barrier();
    }
}

// ============ K3: emissions (W_clf register-resident, FFMA2) ==============
// grid (32 b, 2 tchunk), 256 threads: k = tid>>3, c8 = tid&7
__global__ void __launch_bounds__(256) k_emis(
    const int* __restrict__ lengths,
    const float* __restrict__ Wclf, const float* __restrict__ bclf)
{
    const int b = blockIdx.x;
    const int tc = blockIdx.y;
    const int tid = threadIdx.x;
    const int k = tid >> 3;
    const int c8 = tid & 7;
    const int L = __ldg(&lengths[b]);

    ull wreg[32];
#pragma unroll
    for (int q = 0; q < 32; q++) {
        int p = q * 8 + c8;
        wreg[q] = pack2(__ldg(&Wclf[(size_t)k * 512 + 2 * p]),
                        __ldg(&Wclf[(size_t)k * 512 + 2 * p + 1]));
    }
    const float bias = __ldg(&bclf[k]);

    __shared__ float hs[2][512];

    auto load_row = [&](int t, float& v0, float& v1) {
        int i0 = tid, i1 = tid + 256;
        // i0 < 256 -> forward h
        v0 = d_hall[(((size_t)0 * TT + t) * BB + b) * HH + i0];
        int st = (t < L) ? (L - 1 - t) : t;
        v1 = d_hall[(((size_t)1 * TT + st) * BB + b) * HH + (i1 - 256)];
    };

    float v0, v1;
    load_row(tc * 256, v0, v1);
    for (int tt = 0; tt < 256; tt++) {
        const int t = tc * 256 + tt;
        const int par = tt & 1;
        hs[par][tid] = v0;
        hs[par][tid + 256] = v1;
        __syncthreads();
        if (tt + 1 < 256) load_row(t + 1, v0, v1);

        ull acc = 0ull;
#pragma unroll
        for (int q = 0; q < 32; q++) {
            int p = q * 8 + c8;
            ull hp = *reinterpret_cast<const ull*>(&hs[par][2 * p]);
            acc = ffma2(wreg[q], hp, acc);
        }
        float lo, hi;
        unpack2(acc, lo, hi);
        float tot = lo + hi;
#pragma unroll
        for (int d = 1; d < 8; d <<= 1)
            tot += __shfl_xor_sync(0xffffffffu, tot, d);
        if (c8 == 0)
            d_em[((size_t)b * TT + t) * KK + k] = tot + bias;
    }
}

// ============ K4: CRF forward + Viterbi, 2 warps per batch ================
__global__ void __launch_bounds__(64) k_crf(
    const int* __restrict__ lengths, const int* __restrict__ targets,
    const float* __restrict__ st, const float* __restrict__ en,
    const float* __restrict__ trans)
{
    const int b = blockIdx.x;
    const int wid = threadIdx.x >> 5;
    const int j = threadIdx.x & 31;
    const int L = __ldg(&lengths[b]);

    float trj[32];
#pragma unroll
    for (int i = 0; i < 32; i++) trj[i] = __ldg(&trans[i * 32 + j]);

    float e0 = __ldg(&d_em[((size_t)b * TT + 0) * KK + j]);

    if (wid == 0) {
        // CRF forward
        float alpha = __ldg(&st[j]) + e0;
        for (int t = 1; t < L; t++) {
            float e = __ldg(&d_em[((size_t)b * TT + t) * KK + j]);
            float av[32];
            float m = -1e30f;
#pragma unroll
            for (int i = 0; i < 32; i++) {
                av[i] = __shfl_sync(0xffffffffu, alpha, i) + trj[i];
                m = fmaxf(m, av[i]);
            }
            float ssum = 0.f;
#pragma unroll
            for (int i = 0; i < 32; i++) ssum += __expf(av[i] - m);
            alpha = m + __logf(ssum) + e;
        }
        // logZ
        float a = alpha + __ldg(&en[j]);
        float m = a, ssum;
#pragma unroll
        for (int o = 16; o; o >>= 1) m = fmaxf(m, __shfl_xor_sync(0xffffffffu, m, o));
        ssum = __expf(a - m);
#pragma unroll
        for (int o = 16; o; o >>= 1) ssum += __shfl_xor_sync(0xffffffffu, ssum, o);
        float logZ = m + __logf(ssum);
        // numerator (lane-parallel over t)
        float np = 0.f;
        for (int t = 1 + j; t < L; t += 32) {
            int pt = __ldg(&targets[b * TT + t - 1]);
            int ct = __ldg(&targets[b * TT + t]);
            np += __ldg(&trans[pt * 32 + ct]) + __ldg(&d_em[((size_t)b * TT + t) * KK + ct]);
        }
#pragma unroll
        for (int o = 16; o; o >>= 1) np += __shfl_xor_sync(0xffffffffu, np, o);
        if (j == 0) {
            int tg0 = __ldg(&targets[b * TT + 0]);
            int tgl = __ldg(&targets[b * TT + L - 1]);
            float num = __ldg(&st[tg0]) + __ldg(&d_em[((size_t)b * TT) * KK + tg0]) + np + __ldg(&en[tgl]);
            d_nll[b] = num - logZ;
        }
    } else {
        // Viterbi forward
        float sc = __ldg(&st[j]) + e0;
        for (int t = 1; t < L; t++) {
            float e = __ldg(&d_em[((size_t)b * TT + t) * KK + j]);
            float bm = -1e30f;
            int bi = 0;
#pragma unroll
            for (int i = 0; i < 32; i++) {
                float v = __shfl_sync(0xffffffffu, sc, i) + trj[i];
                if (v > bm) { bm = v; bi = i; }   // ascending i -> first max kept
            }
            d_hist[((size_t)b * 511 + (t - 1)) * KK + j] = (unsigned char)bi;
            sc = bm + e;
        }
        float bm = sc + __ldg(&en[j]);
        int bi = j;
#pragma unroll
        for (int o = 16; o; o >>= 1) {
            float om = __shfl_xor_sync(0xffffffffu, bm, o);
            int oi = __shfl_xor_sync(0xffffffffu, bi, o);
            if (om > bm || (om == bm && oi < bi)) { bm = om; bi = oi; }
        }
        if (j == 0) d_last[b] = bi;
    }
}

// ============ K5: backtrack (smem-staged hist) + loss =====================
__global__ void __launch_bounds__(128) k_back(
    const int* __restrict__ lengths, float* __restrict__ out, int out_size)
{
    const int b = blockIdx.x;
    const int tid = threadIdx.x;
    const bool has_loss = (out_size >= BB * TT + 1);
    const int off = has_loss ? 1 : 0;
    if (out_size < BB * TT) {
        if (b == 0 && tid == 0 && out_size >= 1) {
            float acc = 0.f;
            for (int q = 0; q < BB; q++) acc += d_nll[q];
            out[0] = -acc / (float)BB;
        }
        return;
    }
    __shared__ __align__(16) unsigned char hist_s[511 * KK];
    __shared__ int path[TT];
    {
        const int4* src = reinterpret_cast<const int4*>(&d_hist[(size_t)b * 511 * KK]);
        int4* dst = reinterpret_cast<int4*>(hist_s);
        for (int i = tid; i < (511 * KK) / 16; i += 128) dst[i] = src[i];
    }
    __syncthreads();
    const int L = lengths[b];
    if (tid == 0) {
        int tag = d_last[b];
        path[TT - 1] = tag;
        for (int s = TT - 2; s >= 0; s--) {
            int t = s + 1;
            int prev = (t < L) ? (int)hist_s[s * KK + tag] : tag;
            path[s] = prev;
            tag = prev;
        }
    }
    __syncthreads();
    for (int s = tid; s < TT; s += 128)
        out[off + b * TT + s] = (s < L) ? (float)path[s] : 0.f;
    if (b == 0 && tid == 0 && has_loss) {
        float acc = 0.f;
        for (int q = 0; q < BB; q++) acc += d_nll[q];
        out[0] = -acc / (float)BB;
    }
}

// ---------------- launch ----------------
extern "C" void kernel_launch(void* const* d_in, const int* in_sizes, int n_in,
                              void* d_out, int out_size)
{
    const float* x      = (const float*)d_in[0];
    const int* lengths  = (const int*)d_in[1];
    const int* targets  = (const int*)d_in[3];
    const float* Wihf   = (const float*)d_in[4];
    const float* Whhf   = (const float*)d_in[5];
    const float* bf_    = (const float*)d_in[6];
    const float* Wihb   = (const float*)d_in[7];
    const float* Whhb   = (const float*)d_in[8];
    const float* bb_    = (const float*)d_in[9];
    const float* Wclf   = (const float*)d_in[10];
    const float* bclf   = (const float*)d_in[11];
    const float* st     = (const float*)d_in[12];
    const float* en     = (const float*)d_in[13];
    const float* tr     = (const float*)d_in[14];

    k_pre_gemm<<<dim3(128, 16, 2), 256>>>(x, lengths, Wihf, bf_, Wihb, bb_);
    k_lstm<<<NBLK, 256>>>(Whhf, Whhb);
    k_emis<<<dim3(32, 2), 256>>>(lengths, Wclf, bclf);
    k_crf<<<32, 64>>>(lengths, targets, st, en, tr);
    k_back<<<32, 128>>>(lengths, (float*)d_out, out_size);
}

// round 4
// speedup vs baseline: 1.4680x; 1.1153x over previous
#include <cuda_runtime.h>
#include <cuda_bf16.h>
#include <math.h>

#define TT 512
#define BB 32
#define DD 768
#define HH 256
#define GG 1024   // 4*H
#define KK 32
#define NBLK 128  // recurrence persistent blocks

typedef unsigned long long ull;

// ---------------- packed f32x2 helpers (sm_103a FFMA2) ----------------
__device__ __forceinline__ ull pack2(float x, float y) {
    ull r; asm("mov.b64 %0,{%1,%2};" : "=l"(r) : "f"(x), "f"(y)); return r;
}
__device__ __forceinline__ void unpack2(ull v, float& x, float& y) {
    asm("mov.b64 {%0,%1},%2;" : "=f"(x), "=f"(y) : "l"(v));
}
__device__ __forceinline__ ull ffma2(ull a, ull b, ull c) {
    ull d; asm("fma.rn.f32x2 %0,%1,%2,%3;" : "=l"(d) : "l"(a), "l"(b), "l"(c)); return d;
}
__device__ __forceinline__ ull fadd2(ull a, ull b) {
    ull d; asm("add.rn.f32x2 %0,%1,%2;" : "=l"(d) : "l"(a), "l"(b)); return d;
}

// ---------------- device scratch ----------------
__device__ float d_pre[(size_t)2 * TT * BB * GG];      // [dir][t][b][4H]
__device__ float d_hall[(size_t)2 * TT * BB * HH];     // [dir][t][b][H]
__device__ float d_hbuf[2 * 2 * BB * HH];              // [parity][dir][b][H]
__device__ float d_em[(size_t)BB * TT * KK];           // [b][t][k]
__device__ unsigned char d_hist[(size_t)BB * 511 * KK];
__device__ float d_nll[BB];
__device__ int d_last[BB];
__device__ unsigned d_barc = 0, d_barg = 0;

// ============ K1: pre = x @ W_ih^T + b (128x128 tile, dup-pair FFMA2) ======
#define KC 8
__global__ void __launch_bounds__(256) k_pre_gemm(
    const float* __restrict__ x, const int* __restrict__ lengths,
    const float* __restrict__ Wf, const float* __restrict__ bf_,
    const float* __restrict__ Wb, const float* __restrict__ bb_)
{
    const int dir = blockIdx.z;
    const float* __restrict__ W = dir ? Wb : Wf;
    const float* __restrict__ bias = dir ? bb_ : bf_;
    const int m0 = blockIdx.x * 128;
    const int n0 = blockIdx.y * 128;

    __shared__ __align__(16) float As[2][KC][256];  // A duplicated as pairs: 16KB
    __shared__ __align__(16) float Bs[2][KC][128];  // 8KB

    const int tid = threadIdx.x;
    // loader roles: one float4 of A and one float4 of B per chunk
    const int rowL = tid >> 1;            // 0..127
    const int kq   = (tid & 1) * 4;       // 0 or 4
    int rA = m0 + rowL;
    int tA = rA >> 5, bA = rA & 31;
    int stA = tA;
    if (dir) { int L = __ldg(&lengths[bA]); stA = (tA < L) ? (L - 1 - tA) : tA; }
    const float4* aptr = reinterpret_cast<const float4*>(x + ((size_t)bA * TT + stA) * DD);
    const float4* bptr = reinterpret_cast<const float4*>(W + (size_t)(n0 + rowL) * DD);

    // compute roles: 16x16 thread grid, each 8x8 outputs
    const int trow = tid >> 4;            // 0..15 -> rows trow*8..+8
    const int tcol = tid & 15;            // 0..15 -> cols tcol*8..+8

    ull acc[8][4];
#pragma unroll
    for (int i = 0; i < 8; i++)
#pragma unroll
        for (int p = 0; p < 4; p++) acc[i][p] = 0ull;

    float4 a0 = aptr[(0 + kq) >> 2];
    float4 b0 = bptr[(0 + kq) >> 2];
    {
        const float av[4] = {a0.x, a0.y, a0.z, a0.w};
        const float bv[4] = {b0.x, b0.y, b0.z, b0.w};
#pragma unroll
        for (int q = 0; q < 4; q++) {
            *reinterpret_cast<ull*>(&As[0][kq + q][2 * rowL]) = pack2(av[q], av[q]);
            Bs[0][kq + q][rowL] = bv[q];
        }
    }
    __syncthreads();

    const int NCH = DD / KC;  // 96
    for (int c = 0; c < NCH; c++) {
        const int cb = c & 1;
        if (c + 1 < NCH) {
            int k0 = (c + 1) * KC;
            a0 = aptr[(k0 + kq) >> 2];
            b0 = bptr[(k0 + kq) >> 2];
        }
#pragma unroll
        for (int kk = 0; kk < KC; kk++) {
            ulonglong2 ap0 = *reinterpret_cast<const ulonglong2*>(&As[cb][kk][trow * 16 + 0]);
            ulonglong2 ap1 = *reinterpret_cast<const ulonglong2*>(&As[cb][kk][trow * 16 + 4]);
            ulonglong2 ap2 = *reinterpret_cast<const ulonglong2*>(&As[cb][kk][trow * 16 + 8]);
            ulonglong2 ap3 = *reinterpret_cast<const ulonglong2*>(&As[cb][kk][trow * 16 + 12]);
            ulonglong2 bp0 = *reinterpret_cast<const ulonglong2*>(&Bs[cb][kk][tcol * 8 + 0]);
            ulonglong2 bp1 = *reinterpret_cast<const ulonglong2*>(&Bs[cb][kk][tcol * 8 + 4]);
            ull ar[8] = {ap0.x, ap0.y, ap1.x, ap1.y, ap2.x, ap2.y, ap3.x, ap3.y};
            ull br[4] = {bp0.x, bp0.y, bp1.x, bp1.y};
#pragma unroll
            for (int i = 0; i < 8; i++) {
#pragma unroll
                for (int p = 0; p < 4; p++)
                    acc[i][p] = ffma2(ar[i], br[p], acc[i][p]);
            }
        }
        if (c + 1 < NCH) {
            const int nb = (c + 1) & 1;
            const float av[4] = {a0.x, a0.y, a0.z, a0.w};
            const float bv[4] = {b0.x, b0.y, b0.z, b0.w};
            __syncthreads();
#pragma unroll
            for (int q = 0; q < 4; q++) {
                *reinterpret_cast<ull*>(&As[nb][kq + q][2 * rowL]) = pack2(av[q], av[q]);
                Bs[nb][kq + q][rowL] = bv[q];
            }
            __syncthreads();
        }
    }

    ull bias2[4];
#pragma unroll
    for (int p = 0; p < 4; p++)
        bias2[p] = *reinterpret_cast<const ull*>(&bias[n0 + tcol * 8 + 2 * p]);
#pragma unroll
    for (int i = 0; i < 8; i++) {
        int rr = m0 + trow * 8 + i;
        int t2 = rr >> 5, b2 = rr & 31;
        size_t base = (((size_t)dir * TT + t2) * BB + b2) * GG + n0 + tcol * 8;
#pragma unroll
        for (int p = 0; p < 4; p++)
            *reinterpret_cast<ull*>(&d_pre[base + 2 * p]) = fadd2(acc[i][p], bias2[p]);
    }
}

// ---------------- grid barrier (all NBLK blocks resident) ----------------
__device__ __forceinline__ void grid_barrier()
{
    __syncthreads();
    if (threadIdx.x == 0) {
        volatile unsigned* vg = &d_barg;
        unsigned gen = *vg;
        __threadfence();
        unsigned t = atomicAdd(&d_barc, 1u);
        if (t == NBLK - 1) {
            atomicExch(&d_barc, 0u);
            __threadfence();
            atomicAdd(&d_barg, 1u);
        } else {
            while (*vg == gen) { }
        }
    }
    __syncthreads();
}

__device__ __forceinline__ float sigmoidf_(float v) { return 1.f / (1.f + __expf(-v)); }

// ============ K2: LSTM recurrence (R2-proven: persistent, FFMA2, shfl) =====
__global__ void __launch_bounds__(256, 1) k_lstm(
    const float* __restrict__ Whf, const float* __restrict__ Whb)
{
    const int bid = blockIdx.x;
    const int dir = bid >> 6;
    const int rem = bid & 63;
    const int jc = rem >> 3;
    const int bg = rem & 7;
    const float* __restrict__ Whh = dir ? Whb : Whf;
    const int tid = threadIdx.x;
    const int jj = tid >> 3;
    const int kc = tid & 7;
    const int j = jc * 32 + jj;

    float w[4][32];
#pragma unroll
    for (int g = 0; g < 4; g++)
#pragma unroll
        for (int kk = 0; kk < 32; kk++)
            w[g][kk] = __ldg(&Whh[(size_t)(g * HH + j) * HH + (kk * 8 + kc)]);

    __shared__ __align__(16) float h_s[2][HH][4];
    __shared__ float pre_s[2][512];

    float cst[4] = {0.f, 0.f, 0.f, 0.f};

    for (int q = 0; q < 4; q++) {
        int i = tid + q * 256;
        int b = i >> 8, k = i & 255;
        d_hbuf[((0 * 2 + dir) * BB + bg * 4 + b) * HH + k] = 0.f;
    }
    __threadfence();
    grid_barrier();

    for (int t = 0; t < TT; t++) {
        const int par = t & 1;
        float pv0, pv1, hv[4];
        {
            size_t pbase = (((size_t)dir * TT + t) * BB + bg * 4) * GG;
            int i0 = tid, i1 = tid + 256;
            pv0 = __ldcg(&d_pre[pbase + (size_t)((i0 >> 5) & 3) * GG + (i0 >> 7) * HH + jc * 32 + (i0 & 31)]);
            pv1 = __ldcg(&d_pre[pbase + (size_t)((i1 >> 5) & 3) * GG + (i1 >> 7) * HH + jc * 32 + (i1 & 31)]);
        }
#pragma unroll
        for (int q = 0; q < 4; q++) {
            int i = tid + q * 256;
            int b = i >> 8, k = i & 255;
            hv[q] = __ldcg(&d_hbuf[((par * 2 + dir) * BB + bg * 4 + b) * HH + k]);
        }
        pre_s[par][tid] = pv0;
        pre_s[par][tid + 256] = pv1;
#pragma unroll
        for (int q = 0; q < 4; q++) {
            int i = tid + q * 256;
            h_s[par][i & 255][i >> 8] = hv[q];
        }
        __syncthreads();

        ull acc[4][2];
#pragma unroll
        for (int g = 0; g < 4; g++) { acc[g][0] = 0ull; acc[g][1] = 0ull; }
#pragma unroll
        for (int kk = 0; kk < 32; kk++) {
            int k = kk * 8 + kc;
            ull hp0 = *reinterpret_cast<const ull*>(&h_s[par][k][0]);
            ull hp1 = *reinterpret_cast<const ull*>(&h_s[par][k][2]);
#pragma unroll
            for (int g = 0; g < 4; g++) {
                ull wd = pack2(w[g][kk], w[g][kk]);
                acc[g][0] = ffma2(wd, hp0, acc[g][0]);
                acc[g][1] = ffma2(wd, hp1, acc[g][1]);
            }
        }
        float s[4][4];
#pragma unroll
        for (int g = 0; g < 4; g++) {
            unpack2(acc[g][0], s[g][0], s[g][1]);
            unpack2(acc[g][1], s[g][2], s[g][3]);
        }
#pragma unroll
        for (int d = 1; d < 8; d <<= 1)
#pragma unroll
            for (int g = 0; g < 4; g++)
#pragma unroll
                for (int b = 0; b < 4; b++)
                    s[g][b] += __shfl_xor_sync(0xffffffffu, s[g][b], d);

        if (kc == 0) {
#pragma unroll
            for (int b = 0; b < 4; b++) {
                float gi = s[0][b] + pre_s[par][0 * 128 + b * 32 + jj];
                float gf = s[1][b] + pre_s[par][1 * 128 + b * 32 + jj];
                float gg = s[2][b] + pre_s[par][2 * 128 + b * 32 + jj];
                float go = s[3][b] + pre_s[par][3 * 128 + b * 32 + jj];
                float c = sigmoidf_(gf) * cst[b] + sigmoidf_(gi) * tanhf(gg);
                cst[b] = c;
                float h = sigmoidf_(go) * tanhf(c);
                int gb = bg * 4 + b;
                __stcg(&d_hbuf[(((par ^ 1) * 2 + dir) * BB + gb) * HH + j], h);
                d_hall[(((size_t)dir * TT + t) * BB + gb) * HH + j] = h;
            }
        }
        __threadfence();
        grid_barrier();
    }
}

// ============ K3: emissions (W_clf register-resident, FFMA2) ==============
__global__ void __launch_bounds__(256) k_emis(
    const int* __restrict__ lengths,
    const float* __restrict__ Wclf, const float* __restrict__ bclf)
{
    const int b = blockIdx.x;
    const int tc = blockIdx.y;
    const int tid = threadIdx.x;
    const int k = tid >> 3;
    const int c8 = tid & 7;
    const int L = __ldg(&lengths[b]);

    ull wreg[32];
#pragma unroll
    for (int q = 0; q < 32; q++) {
        int p = q * 8 + c8;
        wreg[q] = pack2(__ldg(&Wclf[(size_t)k * 512 + 2 * p]),
                        __ldg(&Wclf[(size_t)k * 512 + 2 * p + 1]));
    }
    const float bias = __ldg(&bclf[k]);

    __shared__ float hs[2][512];

    auto load_row = [&](int t, float& v0, float& v1) {
        v0 = d_hall[(((size_t)0 * TT + t) * BB + b) * HH + tid];
        int st = (t < L) ? (L - 1 - t) : t;
        v1 = d_hall[(((size_t)1 * TT + st) * BB + b) * HH + tid];
    };

    float v0, v1;
    load_row(tc * 256, v0, v1);
    for (int tt = 0; tt < 256; tt++) {
        const int t = tc * 256 + tt;
        const int par = tt & 1;
        hs[par][tid] = v0;
        hs[par][tid + 256] = v1;
        __syncthreads();
        if (tt + 1 < 256) load_row(t + 1, v0, v1);

        ull acc = 0ull;
#pragma unroll
        for (int q = 0; q < 32; q++) {
            int p = q * 8 + c8;
            acc = ffma2(wreg[q], *reinterpret_cast<const ull*>(&hs[par][2 * p]), acc);
        }
        float lo, hi;
        unpack2(acc, lo, hi);
        float tot = lo + hi;
#pragma unroll
        for (int d = 1; d < 8; d <<= 1)
            tot += __shfl_xor_sync(0xffffffffu, tot, d);
        if (c8 == 0)
            d_em[((size_t)b * TT + t) * KK + k] = tot + bias;
    }
}

// ============ K4: CRF forward + Viterbi, 2 warps per batch ================
__global__ void __launch_bounds__(64) k_crf(
    const int* __restrict__ lengths, const int* __restrict__ targets,
    const float* __restrict__ st, const float* __restrict__ en,
    const float* __restrict__ trans)
{
    const int b = blockIdx.x;
    const int wid = threadIdx.x >> 5;
    const int j = threadIdx.x & 31;
    const int L = __ldg(&lengths[b]);
    float e0 = __ldg(&d_em[((size_t)b * TT + 0) * KK + j]);

    if (wid == 0) {
        // lse_i(alpha_i + tr_ij) = m + log(sum_i exp(alpha_i - m) * exp(tr_ij))
        float etr[32];
#pragma unroll
        for (int i = 0; i < 32; i++) etr[i] = __expf(__ldg(&trans[i * 32 + j]));
        float alpha = __ldg(&st[j]) + e0;
        float e = (L > 1) ? __ldg(&d_em[((size_t)b * TT + 1) * KK + j]) : 0.f;
        for (int t = 1; t < L; t++) {
            float e_cur = e;
            if (t + 1 < L) e = __ldg(&d_em[((size_t)b * TT + t + 1) * KK + j]);
            float m = alpha;
#pragma unroll
            for (int o = 16; o; o >>= 1) m = fmaxf(m, __shfl_xor_sync(0xffffffffu, m, o));
            float ea = __expf(alpha - m);
            float ssum = 0.f;
#pragma unroll
            for (int i = 0; i < 32; i++)
                ssum = fmaf(__shfl_sync(0xffffffffu, ea, i), etr[i], ssum);
            alpha = m + __logf(ssum) + e_cur;
        }
        float a = alpha + __ldg(&en[j]);
        float m2 = a;
#pragma unroll
        for (int o = 16; o; o >>= 1) m2 = fmaxf(m2, __shfl_xor_sync(0xffffffffu, m2, o));
        float ssum2 = __expf(a - m2);
#pragma unroll
        for (int o = 16; o; o >>= 1) ssum2 += __shfl_xor_sync(0xffffffffu, ssum2, o);
        float logZ = m2 + __logf(ssum2);
        float np = 0.f;
        for (int t = 1 + j; t < L; t += 32) {
            int pt = __ldg(&targets[b * TT + t - 1]);
            int ct = __ldg(&targets[b * TT + t]);
            np += __ldg(&trans[pt * 32 + ct]) + __ldg(&d_em[((size_t)b * TT + t) * KK + ct]);
        }
#pragma unroll
        for (int o = 16; o; o >>= 1) np += __shfl_xor_sync(0xffffffffu, np, o);
        if (j == 0) {
            int tg0 = __ldg(&targets[b * TT + 0]);
            int tgl = __ldg(&targets[b * TT + L - 1]);
            float num = __ldg(&st[tg0]) + __ldg(&d_em[((size_t)b * TT) * KK + tg0]) + np + __ldg(&en[tgl]);
            d_nll[b] = num - logZ;
        }
    } else {
        float trj[32];
#pragma unroll
        for (int i = 0; i < 32; i++) trj[i] = __ldg(&trans[i * 32 + j]);
        float sc = __ldg(&st[j]) + e0;
        float e = (L > 1) ? __ldg(&d_em[((size_t)b * TT + 1) * KK + j]) : 0.f;
        for (int t = 1; t < L; t++) {
            float e_cur = e;
            if (t + 1 < L) e = __ldg(&d_em[((size_t)b * TT + t + 1) * KK + j]);
            float bm = -1e30f;
            int bi = 0;
#pragma unroll
            for (int i = 0; i < 32; i++) {
                float v = __shfl_sync(0xffffffffu, sc, i) + trj[i];
                if (v > bm) { bm = v; bi = i; }
            }
            d_hist[((size_t)b * 511 + (t - 1)) * KK + j] = (unsigned char)bi;
            sc = bm + e_cur;
        }
        float bm = sc + __ldg(&en[j]);
        int bi = j;
#pragma unroll
        for (int o = 16; o; o >>= 1) {
            float om = __shfl_xor_sync(0xffffffffu, bm, o);
            int oi = __shfl_xor_sync(0xffffffffu, bi, o);
            if (om > bm || (om == bm && oi < bi)) { bm = om; bi = oi; }
        }
        if (j == 0) d_last[b] = bi;
    }
}

// ============ K5: backtrack (smem-staged hist) + loss =====================
__global__ void __launch_bounds__(128) k_back(
    const int* __restrict__ lengths, float* __restrict__ out, int out_size)
{
    const int b = blockIdx.x;
    const int tid = threadIdx.x;
    const bool has_loss = (out_size >= BB * TT + 1);
    const int off = has_loss ? 1 : 0;
    if (out_size < BB * TT) {
        if (b == 0 && tid == 0 && out_size >= 1) {
            float acc = 0.f;
            for (int q = 0; q < BB; q++) acc += d_nll[q];
            out[0] = -acc / (float)BB;
        }
        return;
    }
    __shared__ __align__(16) unsigned char hist_s[511 * KK];
    __shared__ int path[TT];
    {
        const int4* src = reinterpret_cast<const int4*>(&d_hist[(size_t)b * 511 * KK]);
        int4* dst = reinterpret_cast<int4*>(hist_s);
        for (int i = tid; i < (511 * KK) / 16; i += 128) dst[i] = src[i];
    }
    __syncthreads();
    const int L = lengths[b];
    if (tid == 0) {
        int tag = d_last[b];
        path[TT - 1] = tag;
        for (int s = TT - 2; s >= 0; s--) {
            int t = s + 1;
            int prev = (t < L) ? (int)hist_s[s * KK + tag] : tag;
            path[s] = prev;
            tag = prev;
        }
    }
    __syncthreads();
    for (int s = tid; s < TT; s += 128)
        out[off + b * TT + s] = (s < L) ? (float)path[s] : 0.f;
    if (b == 0 && tid == 0 && has_loss) {
        float acc = 0.f;
        for (int q = 0; q < BB; q++) acc += d_nll[q];
        out[0] = -acc / (float)BB;
    }
}

// ---------------- launch ----------------
extern "C" void kernel_launch(void* const* d_in, const int* in_sizes, int n_in,
                              void* d_out, int out_size)
{
    const float* x      = (const float*)d_in[0];
    const int* lengths  = (const int*)d_in[1];
    const int* targets  = (const int*)d_in[3];
    const float* Wihf   = (const float*)d_in[4];
    const float* Whhf   = (const float*)d_in[5];
    const float* bf_    = (const float*)d_in[6];
    const float* Wihb   = (const float*)d_in[7];
    const float* Whhb   = (const float*)d_in[8];
    const float* bb_    = (const float*)d_in[9];
    const float* Wclf   = (const float*)d_in[10];
    const float* bclf   = (const float*)d_in[11];
    const float* st     = (const float*)d_in[12];
    const float* en     = (const float*)d_in[13];
    const float* tr     = (const float*)d_in[14];

    k_pre_gemm<<<dim3(128, 8, 2), 256>>>(x, lengths, Wihf, bf_, Wihb, bb_);
    k_lstm<<<NBLK, 256>>>(Whhf, Whhb);
    k_emis<<<dim3(32, 2), 256>>>(lengths, Wclf, bclf);
    k_crf<<<32, 64>>>(lengths, targets, st, en, tr);
    k_back<<<32, 128>>>(lengths, (float*)d_out, out_size);
}

// round 7
// speedup vs baseline: 1.5811x; 1.0771x over previous
#include <cuda_runtime.h>
#include <cuda_bf16.h>
#include <math.h>

#define TT 512
#define BB 32
#define DD 768
#define HH 256
#define GG 1024   // 4*H
#define KK 32

typedef unsigned long long ull;

// ---------------- packed f32x2 helpers (sm_103a FFMA2) ----------------
__device__ __forceinline__ ull pack2(float x, float y) {
    ull r; asm("mov.b64 %0,{%1,%2};" : "=l"(r) : "f"(x), "f"(y)); return r;
}
__device__ __forceinline__ void unpack2(ull v, float& x, float& y) {
    asm("mov.b64 {%0,%1},%2;" : "=f"(x), "=f"(y) : "l"(v));
}
__device__ __forceinline__ ull ffma2(ull a, ull b, ull c) {
    ull d; asm("fma.rn.f32x2 %0,%1,%2,%3;" : "=l"(d) : "l"(a), "l"(b), "l"(c)); return d;
}
__device__ __forceinline__ ull fadd2(ull a, ull b) {
    ull d; asm("add.rn.f32x2 %0,%1,%2;" : "=l"(d) : "l"(a), "l"(b)); return d;
}

// ---------------- device scratch ----------------
__device__ float d_pre[(size_t)2 * TT * BB * GG];      // [dir][t][b][4H]
__device__ float d_hall[(size_t)2 * TT * BB * HH];     // [dir][t][b][H]
__device__ float d_hbuf[2 * 2 * BB * HH];              // [parity][dir][b][H]
__device__ float d_em[(size_t)BB * TT * KK];           // [b][t][k]
__device__ unsigned char d_hist[(size_t)BB * 511 * KK];
__device__ float d_nll[BB];
__device__ int d_last[BB];
__device__ unsigned d_cnt[16 * 32];                    // per-group counters, 128B apart

// ============ K1: pre = x @ W_ih^T + b (128x128 tile, dup-pair FFMA2) ======
#define KC 8
__global__ void __launch_bounds__(256) k_pre_gemm(
    const float* __restrict__ x, const int* __restrict__ lengths,
    const float* __restrict__ Wf, const float* __restrict__ bf_,
    const float* __restrict__ Wb, const float* __restrict__ bb_)
{
    // reset k_lstm group counters (graph replays must see zeros)
    if (blockIdx.x == 0 && blockIdx.y == 0 && blockIdx.z == 0 && threadIdx.x < 16)
        d_cnt[threadIdx.x * 32] = 0;

    const int dir = blockIdx.z;
    const float* __restrict__ W = dir ? Wb : Wf;
    const float* __restrict__ bias = dir ? bb_ : bf_;
    const int m0 = blockIdx.x * 128;
    const int n0 = blockIdx.y * 128;

    __shared__ __align__(16) float As[2][KC][256];  // A duplicated as pairs
    __shared__ __align__(16) float Bs[2][KC][128];

    const int tid = threadIdx.x;
    const int rowL = tid >> 1;            // 0..127
    const int kq   = (tid & 1) * 4;       // 0 or 4
    int rA = m0 + rowL;
    int tA = rA >> 5, bA = rA & 31;
    int stA = tA;
    if (dir) { int L = __ldg(&lengths[bA]); stA = (tA < L) ? (L - 1 - tA) : tA; }
    const float4* aptr = reinterpret_cast<const float4*>(x + ((size_t)bA * TT + stA) * DD);
    const float4* bptr = reinterpret_cast<const float4*>(W + (size_t)(n0 + rowL) * DD);

    const int trow = tid >> 4;            // 0..15
    const int tcol = tid & 15;            // 0..15

    ull acc[8][4];
#pragma unroll
    for (int i = 0; i < 8; i++)
#pragma unroll
        for (int p = 0; p < 4; p++) acc[i][p] = 0ull;

    float4 a0 = aptr[(0 + kq) >> 2];
    float4 b0 = bptr[(0 + kq) >> 2];
    {
        const float av[4] = {a0.x, a0.y, a0.z, a0.w};
        const float bv[4] = {b0.x, b0.y, b0.z, b0.w};
#pragma unroll
        for (int q = 0; q < 4; q++) {
            *reinterpret_cast<ull*>(&As[0][kq + q][2 * rowL]) = pack2(av[q], av[q]);
            Bs[0][kq + q][rowL] = bv[q];
        }
    }
    __syncthreads();

    const int NCH = DD / KC;  // 96
    for (int c = 0; c < NCH; c++) {
        const int cb = c & 1;
        if (c + 1 < NCH) {
            int k0 = (c + 1) * KC;
            a0 = aptr[(k0 + kq) >> 2];
            b0 = bptr[(k0 + kq) >> 2];
        }
#pragma unroll
        for (int kk = 0; kk < KC; kk++) {
            ulonglong2 ap0 = *reinterpret_cast<const ulonglong2*>(&As[cb][kk][trow * 16 + 0]);
            ulonglong2 ap1 = *reinterpret_cast<const ulonglong2*>(&As[cb][kk][trow * 16 + 4]);
            ulonglong2 ap2 = *reinterpret_cast<const ulonglong2*>(&As[cb][kk][trow * 16 + 8]);
            ulonglong2 ap3 = *reinterpret_cast<const ulonglong2*>(&As[cb][kk][trow * 16 + 12]);
            ulonglong2 bp0 = *reinterpret_cast<const ulonglong2*>(&Bs[cb][kk][tcol * 8 + 0]);
            ulonglong2 bp1 = *reinterpret_cast<const ulonglong2*>(&Bs[cb][kk][tcol * 8 + 4]);
            ull ar[8] = {ap0.x, ap0.y, ap1.x, ap1.y, ap2.x, ap2.y, ap3.x, ap3.y};
            ull br[4] = {bp0.x, bp0.y, bp1.x, bp1.y};
#pragma unroll
            for (int i = 0; i < 8; i++) {
#pragma unroll
                for (int p = 0; p < 4; p++)
                    acc[i][p] = ffma2(ar[i], br[p], acc[i][p]);
            }
        }
        if (c + 1 < NCH) {
            const int nb = (c + 1) & 1;
            const float av[4] = {a0.x, a0.y, a0.z, a0.w};
            const float bv[4] = {b0.x, b0.y, b0.z, b0.w};
            __syncthreads();
#pragma unroll
            for (int q = 0; q < 4; q++) {
                *reinterpret_cast<ull*>(&As[nb][kq + q][2 * rowL]) = pack2(av[q], av[q]);
                Bs[nb][kq + q][rowL] = bv[q];
            }
            __syncthreads();
        }
    }

    ull bias2[4];
#pragma unroll
    for (int p = 0; p < 4; p++)
        bias2[p] = *reinterpret_cast<const ull*>(&bias[n0 + tcol * 8 + 2 * p]);
#pragma unroll
    for (int i = 0; i < 8; i++) {
        int rr = m0 + trow * 8 + i;
        int t2 = rr >> 5, b2 = rr & 31;
        size_t base = (((size_t)dir * TT + t2) * BB + b2) * GG + n0 + tcol * 8;
#pragma unroll
        for (int p = 0; p < 4; p++)
            *reinterpret_cast<ull*>(&d_pre[base + 2 * p]) = fadd2(acc[i][p], bias2[p]);
    }
}

__device__ __forceinline__ float sigmoidf_(float v) { return 1.f / (1.f + __expf(-v)); }

// ============ K2: LSTM recurrence — per-group (8-block) counter sync =======
// 128 blocks: g = bid>>3 (dir = g>>3, bg = g&7), jc = bid&7.
// Block owns j-slice jc*32..+32 and batches bg*4..+4; exchanges h with its
// 7 group peers via d_hbuf + a monotonic release/acquire counter.
__global__ void __launch_bounds__(256, 1) k_lstm(
    const float* __restrict__ Whf, const float* __restrict__ Whb)
{
    const int bid = blockIdx.x;
    const int g = bid >> 3;
    const int jc = bid & 7;
    const int dir = g >> 3;
    const int bg = g & 7;
    const float* __restrict__ Whh = dir ? Whb : Whf;
    const int tid = threadIdx.x;
    const int jj = tid >> 3;
    const int kc = tid & 7;
    const int j = jc * 32 + jj;
    unsigned* cnt = &d_cnt[g * 32];

    float w[4][32];
#pragma unroll
    for (int gg = 0; gg < 4; gg++)
#pragma unroll
        for (int kk = 0; kk < 32; kk++)
            w[gg][kk] = __ldg(&Whh[(size_t)(gg * HH + j) * HH + (kk * 8 + kc)]);

    __shared__ __align__(16) float h_s[2][HH][4];
    __shared__ float pre_s[2][512];

    float cst[4] = {0.f, 0.f, 0.f, 0.f};

    // zero initial h (this block's j-slice for its 4 batches), then release-add
    if (kc == 0) {
#pragma unroll
        for (int b = 0; b < 4; b++)
            __stcg(&d_hbuf[((0 * 2 + dir) * BB + bg * 4 + b) * HH + j], 0.f);
    }
    __threadfence();
    __syncthreads();
    if (tid == 0)
        asm volatile("red.release.gpu.global.add.u32 [%0],%1;" :: "l"(cnt), "r"(1u) : "memory");

    for (int t = 0; t < TT; t++) {
        const int par = t & 1;
        // wait for all 8 group blocks to have published h for this step
        if (tid == 0) {
            const unsigned target = 8u * (unsigned)(t + 1);
            unsigned v;
            do {
                asm volatile("ld.acquire.gpu.global.u32 %0,[%1];" : "=r"(v) : "l"(cnt));
            } while (v < target);
        }
        __syncthreads();

        float pv0, pv1, hv[4];
        {
            size_t pbase = (((size_t)dir * TT + t) * BB + bg * 4) * GG;
            int i0 = tid, i1 = tid + 256;
            pv0 = __ldcg(&d_pre[pbase + (size_t)((i0 >> 5) & 3) * GG + (i0 >> 7) * HH + jc * 32 + (i0 & 31)]);
            pv1 = __ldcg(&d_pre[pbase + (size_t)((i1 >> 5) & 3) * GG + (i1 >> 7) * HH + jc * 32 + (i1 & 31)]);
        }
#pragma unroll
        for (int q = 0; q < 4; q++) {
            int i = tid + q * 256;
            int b = i >> 8, k = i & 255;
            hv[q] = __ldcg(&d_hbuf[((par * 2 + dir) * BB + bg * 4 + b) * HH + k]);
        }
        pre_s[par][tid] = pv0;
        pre_s[par][tid + 256] = pv1;
#pragma unroll
        for (int q = 0; q < 4; q++) {
            int i = tid + q * 256;
            h_s[par][i & 255][i >> 8] = hv[q];
        }
        __syncthreads();

        ull acc[4][2];
#pragma unroll
        for (int gg = 0; gg < 4; gg++) { acc[gg][0] = 0ull; acc[gg][1] = 0ull; }
#pragma unroll
        for (int kk = 0; kk < 32; kk++) {
            int k = kk * 8 + kc;
            ull hp0 = *reinterpret_cast<const ull*>(&h_s[par][k][0]);
            ull hp1 = *reinterpret_cast<const ull*>(&h_s[par][k][2]);
#pragma unroll
            for (int gg = 0; gg < 4; gg++) {
                ull wd = pack2(w[gg][kk], w[gg][kk]);
                acc[gg][0] = ffma2(wd, hp0, acc[gg][0]);
                acc[gg][1] = ffma2(wd, hp1, acc[gg][1]);
            }
        }
        float s[4][4];
#pragma unroll
        for (int gg = 0; gg < 4; gg++) {
            unpack2(acc[gg][0], s[gg][0], s[gg][1]);
            unpack2(acc[gg][1], s[gg][2], s[gg][3]);
        }
#pragma unroll
        for (int d = 1; d < 8; d <<= 1)
#pragma unroll
            for (int gg = 0; gg < 4; gg++)
#pragma unroll
                for (int b = 0; b < 4; b++)
                    s[gg][b] += __shfl_xor_sync(0xffffffffu, s[gg][b], d);

        if (kc == 0) {
#pragma unroll
            for (int b = 0; b < 4; b++) {
                float gi = s[0][b] + pre_s[par][0 * 128 + b * 32 + jj];
                float gf = s[1][b] + pre_s[par][1 * 128 + b * 32 + jj];
                float gg2 = s[2][b] + pre_s[par][2 * 128 + b * 32 + jj];
                float go = s[3][b] + pre_s[par][3 * 128 + b * 32 + jj];
                float c = sigmoidf_(gf) * cst[b] + sigmoidf_(gi) * tanhf(gg2);
                cst[b] = c;
                float h = sigmoidf_(go) * tanhf(c);
                int gb = bg * 4 + b;
                __stcg(&d_hbuf[(((par ^ 1) * 2 + dir) * BB + gb) * HH + j], h);
                d_hall[(((size_t)dir * TT + t) * BB + gb) * HH + j] = h;
            }
        }
        __threadfence();
        __syncthreads();
        if (tid == 0)
            asm volatile("red.release.gpu.global.add.u32 [%0],%1;" :: "l"(cnt), "r"(1u) : "memory");
    }
}

// ============ K3: emissions (W_clf register-resident, FFMA2) ==============
__global__ void __launch_bounds__(256) k_emis(
    const int* __restrict__ lengths,
    const float* __restrict__ Wclf, const float* __restrict__ bclf)
{
    const int b = blockIdx.x;
    const int tc = blockIdx.y;
    const int tid = threadIdx.x;
    const int k = tid >> 3;
    const int c8 = tid & 7;
    const int L = __ldg(&lengths[b]);

    ull wreg[32];
#pragma unroll
    for (int q = 0; q < 32; q++) {
        int p = q * 8 + c8;
        wreg[q] = pack2(__ldg(&Wclf[(size_t)k * 512 + 2 * p]),
                        __ldg(&Wclf[(size_t)k * 512 + 2 * p + 1]));
    }
    const float bias = __ldg(&bclf[k]);

    __shared__ float hs[2][512];

    auto load_row = [&](int t, float& v0, float& v1) {
        v0 = d_hall[(((size_t)0 * TT + t) * BB + b) * HH + tid];
        int st = (t < L) ? (L - 1 - t) : t;
        v1 = d_hall[(((size_t)1 * TT + st) * BB + b) * HH + tid];
    };

    float v0, v1;
    load_row(tc * 256, v0, v1);
    for (int tt = 0; tt < 256; tt++) {
        const int t = tc * 256 + tt;
        const int par = tt & 1;
        hs[par][tid] = v0;
        hs[par][tid + 256] = v1;
        __syncthreads();
        if (tt + 1 < 256) load_row(t + 1, v0, v1);

        ull acc = 0ull;
#pragma unroll
        for (int q = 0; q < 32; q++) {
            int p = q * 8 + c8;
            acc = ffma2(wreg[q], *reinterpret_cast<const ull*>(&hs[par][2 * p]), acc);
        }
        float lo, hi;
        unpack2(acc, lo, hi);
        float tot = lo + hi;
#pragma unroll
        for (int d = 1; d < 8; d <<= 1)
            tot += __shfl_xor_sync(0xffffffffu, tot, d);
        if (c8 == 0)
            d_em[((size_t)b * TT + t) * KK + k] = tot + bias;
    }
}

// ---------------- warp float max via REDUX (order-preserving int map) -----
__device__ __forceinline__ float warp_max32(float x) {
    int k = __float_as_int(x);
    k = (k >= 0) ? k : (k ^ 0x7fffffff);
    int m = __reduce_max_sync(0xffffffffu, k);
    m = (m >= 0) ? m : (m ^ 0x7fffffff);
    return __int_as_float(m);
}

// ============ K4: CRF forward + Viterbi, 2 warps per batch ================
__global__ void __launch_bounds__(64) k_crf(
    const int* __restrict__ lengths, const int* __restrict__ targets,
    const float* __restrict__ st, const float* __restrict__ en,
    const float* __restrict__ trans)
{
    const int b = blockIdx.x;
    const int wid = threadIdx.x >> 5;
    const int j = threadIdx.x & 31;
    const int L = __ldg(&lengths[b]);
    float e0 = __ldg(&d_em[((size_t)b * TT + 0) * KK + j]);

    if (wid == 0) {
        // lse_i(alpha_i + tr_ij) = m + log(sum_i exp(alpha_i - m) * exp(tr_ij))
        float etr[32];
#pragma unroll
        for (int i = 0; i < 32; i++) etr[i] = __expf(__ldg(&trans[i * 32 + j]));
        float alpha = __ldg(&st[j]) + e0;
        float e = (L > 1) ? __ldg(&d_em[((size_t)b * TT + 1) * KK + j]) : 0.f;
        for (int t = 1; t < L; t++) {
            float e_cur = e;
            if (t + 1 < L) e = __ldg(&d_em[((size_t)b * TT + t + 1) * KK + j]);
            float m = warp_max32(alpha);
            float ea = __expf(alpha - m);
            float s0 = 0.f, s1 = 0.f, s2 = 0.f, s3 = 0.f;
#pragma unroll
            for (int i = 0; i < 32; i += 4) {
                s0 = fmaf(__shfl_sync(0xffffffffu, ea, i + 0), etr[i + 0], s0);
                s1 = fmaf(__shfl_sync(0xffffffffu, ea, i + 1), etr[i + 1], s1);
                s2 = fmaf(__shfl_sync(0xffffffffu, ea, i + 2), etr[i + 2], s2);
                s3 = fmaf(__shfl_sync(0xffffffffu, ea, i + 3), etr[i + 3], s3);
            }
            alpha = m + __logf((s0 + s1) + (s2 + s3)) + e_cur;
        }
        float a = alpha + __ldg(&en[j]);
        float m2 = warp_max32(a);
        float ssum2 = __expf(a - m2);
#pragma unroll
        for (int o = 16; o; o >>= 1) ssum2 += __shfl_xor_sync(0xffffffffu, ssum2, o);
        float logZ = m2 + __logf(ssum2);
        float np = 0.f;
        for (int t = 1 + j; t < L; t += 32) {
            int pt = __ldg(&targets[b * TT + t - 1]);
            int ct = __ldg(&targets[b * TT + t]);
            np += __ldg(&trans[pt * 32 + ct]) + __ldg(&d_em[((size_t)b * TT + t) * KK + ct]);
        }
#pragma unroll
        for (int o = 16; o; o >>= 1) np += __shfl_xor_sync(0xffffffffu, np, o);
        if (j == 0) {
            int tg0 = __ldg(&targets[b * TT + 0]);
            int tgl = __ldg(&targets[b * TT + L - 1]);
            float num = __ldg(&st[tg0]) + __ldg(&d_em[((size_t)b * TT) * KK + tg0]) + np + __ldg(&en[tgl]);
            d_nll[b] = num - logZ;
        }
    } else {
        float trj[32];
#pragma unroll
        for (int i = 0; i < 32; i++) trj[i] = __ldg(&trans[i * 32 + j]);
        float sc = __ldg(&st[j]) + e0;
        float e = (L > 1) ? __ldg(&d_em[((size_t)b * TT + 1) * KK + j]) : 0.f;
        for (int t = 1; t < L; t++) {
            float e_cur = e;
            if (t + 1 < L) e = __ldg(&d_em[((size_t)b * TT + t + 1) * KK + j]);
            float bm = -1e30f;
            int bi = 0;
#pragma unroll
            for (int i = 0; i < 32; i++) {
                float v = __shfl_sync(0xffffffffu, sc, i) + trj[i];
                bi = (v > bm) ? i : bi;        // ascending i -> first max kept
                bm = fmaxf(bm, v);
            }
            d_hist[((size_t)b * 511 + (t - 1)) * KK + j] = (unsigned char)bi;
            sc = bm + e_cur;
        }
        float bm = sc + __ldg(&en[j]);
        int bi = j;
#pragma unroll
        for (int o = 16; o; o >>= 1) {
            float om = __shfl_xor_sync(0xffffffffu, bm, o);
            int oi = __shfl_xor_sync(0xffffffffu, bi, o);
            if (om > bm || (om == bm && oi < bi)) { bm = om; bi = oi; }
        }
        if (j == 0) d_last[b] = bi;
    }
}

// ============ K5: backtrack (smem-staged hist) + loss =====================
__global__ void __launch_bounds__(128) k_back(
    const int* __restrict__ lengths, float* __restrict__ out, int out_size)
{
    const int b = blockIdx.x;
    const int tid = threadIdx.x;
    const bool has_loss = (out_size >= BB * TT + 1);
    const int off = has_loss ? 1 : 0;
    if (out_size < BB * TT) {
        if (b == 0 && tid == 0 && out_size >= 1) {
            float acc = 0.f;
            for (int q = 0; q < BB; q++) acc += d_nll[q];
            out[0] = -acc / (float)BB;
        }
        return;
    }
    __shared__ __align__(16) unsigned char hist_s[511 * KK];
    __shared__ int path[TT];
    {
        const int4* src = reinterpret_cast<const int4*>(&d_hist[(size_t)b * 511 * KK]);
        int4* dst = reinterpret_cast<int4*>(hist_s);
        for (int i = tid; i < (511 * KK) / 16; i += 128) dst[i] = src[i];
    }
    __syncthreads();
    const int L = lengths[b];
    if (tid == 0) {
        int tag = d_last[b];
        path[TT - 1] = tag;
        for (int s = TT - 2; s >= 0; s--) {
            int t = s + 1;
            int prev = (t < L) ? (int)hist_s[s * KK + tag] : tag;
            path[s] = prev;
            tag = prev;
        }
    }
    __syncthreads();
    for (int s = tid; s < TT; s += 128)
        out[off + b * TT + s] = (s < L) ? (float)path[s] : 0.f;
    if (b == 0 && tid == 0 && has_loss) {
        float acc = 0.f;
        for (int q = 0; q < BB; q++) acc += d_nll[q];
        out[0] = -acc / (float)BB;
    }
}

// ---------------- launch ----------------
extern "C" void kernel_launch(void* const* d_in, const int* in_sizes, int n_in,
                              void* d_out, int out_size)
{
    const float* x      = (const float*)d_in[0];
    const int* lengths  = (const int*)d_in[1];
    const int* targets  = (const int*)d_in[3];
    const float* Wihf   = (const float*)d_in[4];
    const float* Whhf   = (const float*)d_in[5];
    const float* bf_    = (const float*)d_in[6];
    const float* Wihb   = (const float*)d_in[7];
    const float* Whhb   = (const float*)d_in[8];
    const float* bb_    = (const float*)d_in[9];
    const float* Wclf   = (const float*)d_in[10];
    const float* bclf   = (const float*)d_in[11];
    const float* st     = (const float*)d_in[12];
    const float* en     = (const float*)d_in[13];
    const float* tr     = (const float*)d_in[14];

    k_pre_gemm<<<dim3(128, 8, 2), 256>>>(x, lengths, Wihf, bf_, Wihb, bb_);
    k_lstm<<<128, 256>>>(Whhf, Whhb);
    k_emis<<<dim3(32, 2), 256>>>(lengths, Wclf, bclf);
    k_crf<<<32, 64>>>(lengths, targets, st, en, tr);
    k_back<<<32, 128>>>(lengths, (float*)d_out, out_size);
}

// round 8
// speedup vs baseline: 1.7548x; 1.1099x over previous
#include <cuda_runtime.h>
#include <cuda_bf16.h>
#include <math.h>

#define TT 512
#define BB 32
#define DD 768
#define HH 256
#define GG 1024   // 4*H
#define KK 32
#define KC 8

typedef unsigned long long ull;

// ---------------- packed f32x2 helpers (sm_103a FFMA2) ----------------
__device__ __forceinline__ ull pack2(float x, float y) {
    ull r; asm("mov.b64 %0,{%1,%2};" : "=l"(r) : "f"(x), "f"(y)); return r;
}
__device__ __forceinline__ void unpack2(ull v, float& x, float& y) {
    asm("mov.b64 {%0,%1},%2;" : "=f"(x), "=f"(y) : "l"(v));
}
__device__ __forceinline__ ull ffma2(ull a, ull b, ull c) {
    ull d; asm("fma.rn.f32x2 %0,%1,%2,%3;" : "=l"(d) : "l"(a), "l"(b), "l"(c)); return d;
}
__device__ __forceinline__ ull fadd2(ull a, ull b) {
    ull d; asm("add.rn.f32x2 %0,%1,%2;" : "=l"(d) : "l"(a), "l"(b)); return d;
}

// ---------------- device scratch ----------------
__device__ float d_pre[(size_t)2 * TT * BB * GG];      // [dir][t][b][4H]
__device__ float d_hall[(size_t)2 * TT * BB * HH];     // [dir][t][b][H]
__device__ float d_hbuf[2 * 2 * BB * HH];              // [parity][dir][b][H]
__device__ float d_em[(size_t)BB * TT * KK];           // [b][t][k]
__device__ unsigned char d_hist[(size_t)BB * 511 * KK];
__device__ float d_nll[BB];
__device__ int d_last[BB];
__device__ unsigned d_cnt[16 * 32];                    // per-LSTM-group h counters (128B apart)
__device__ unsigned d_pcnt[2 * 128];                   // per-(dir, tgroup4) pre-tile counters

// ---------------- shared-memory overlay ----------------
struct GemmS {
    float As[2][KC][256];  // A duplicated as f32 pairs
    float Bs[2][KC][128];
};
struct LstmS {
    float h_s[2][HH][4];
    float pre_s[2][512];
};
union SmemU {
    GemmS g;
    LstmS l;
};

__device__ __forceinline__ float sigmoidf_(float v) { return 1.f / (1.f + __expf(-v)); }

// ============ K0: reset counters (graph replays must see zeros) ===========
__global__ void k_init()
{
    int i = threadIdx.x;
    if (i < 2 * 128) d_pcnt[i] = 0;
    for (int q = i; q < 16 * 32; q += 256) d_cnt[q] = 0;
}

// ---------------- GEMM role: one 128x128 tile of pre = x@W_ih^T + b -------
__device__ __forceinline__ void gemm_role(int gbid, GemmS& S,
    const float* __restrict__ x, const int* __restrict__ lengths,
    const float* __restrict__ Wf, const float* __restrict__ bf_,
    const float* __restrict__ Wb, const float* __restrict__ bb_)
{
    const int tg  = gbid >> 4;            // 0..127 : t-group of 4
    const int sub = gbid & 15;
    const int dir = sub >> 3;
    const int n0  = (sub & 7) * 128;
    const int m0  = tg * 128;
    const float* __restrict__ W    = dir ? Wb : Wf;
    const float* __restrict__ bias = dir ? bb_ : bf_;

    const int tid  = threadIdx.x;
    const int rowL = tid >> 1;            // 0..127
    const int kq   = (tid & 1) * 4;       // 0 or 4
    int rA = m0 + rowL;
    int tA = rA >> 5, bA = rA & 31;
    int stA = tA;
    if (dir) { int L = __ldg(&lengths[bA]); stA = (tA < L) ? (L - 1 - tA) : tA; }
    const float4* aptr = reinterpret_cast<const float4*>(x + ((size_t)bA * TT + stA) * DD);
    const float4* bptr = reinterpret_cast<const float4*>(W + (size_t)(n0 + rowL) * DD);

    const int trow = tid >> 4;            // 0..15
    const int tcol = tid & 15;            // 0..15

    ull acc[8][4];
#pragma unroll
    for (int i = 0; i < 8; i++)
#pragma unroll
        for (int p = 0; p < 4; p++) acc[i][p] = 0ull;

    float4 a0 = aptr[(0 + kq) >> 2];
    float4 b0 = bptr[(0 + kq) >> 2];
    {
        const float av[4] = {a0.x, a0.y, a0.z, a0.w};
        const float bv[4] = {b0.x, b0.y, b0.z, b0.w};
#pragma unroll
        for (int q = 0; q < 4; q++) {
            *reinterpret_cast<ull*>(&S.As[0][kq + q][2 * rowL]) = pack2(av[q], av[q]);
            S.Bs[0][kq + q][rowL] = bv[q];
        }
    }
    __syncthreads();

    const int NCH = DD / KC;  // 96
    for (int c = 0; c < NCH; c++) {
        const int cb = c & 1;
        if (c + 1 < NCH) {
            int k0 = (c + 1) * KC;
            a0 = aptr[(k0 + kq) >> 2];
            b0 = bptr[(k0 + kq) >> 2];
        }
#pragma unroll
        for (int kk = 0; kk < KC; kk++) {
            ulonglong2 ap0 = *reinterpret_cast<const ulonglong2*>(&S.As[cb][kk][trow * 16 + 0]);
            ulonglong2 ap1 = *reinterpret_cast<const ulonglong2*>(&S.As[cb][kk][trow * 16 + 4]);
            ulonglong2 ap2 = *reinterpret_cast<const ulonglong2*>(&S.As[cb][kk][trow * 16 + 8]);
            ulonglong2 ap3 = *reinterpret_cast<const ulonglong2*>(&S.As[cb][kk][trow * 16 + 12]);
            ulonglong2 bp0 = *reinterpret_cast<const ulonglong2*>(&S.Bs[cb][kk][tcol * 8 + 0]);
            ulonglong2 bp1 = *reinterpret_cast<const ulonglong2*>(&S.Bs[cb][kk][tcol * 8 + 4]);
            ull ar[8] = {ap0.x, ap0.y, ap1.x, ap1.y, ap2.x, ap2.y, ap3.x, ap3.y};
            ull br[4] = {bp0.x, bp0.y, bp1.x, bp1.y};
#pragma unroll
            for (int i = 0; i < 8; i++) {
#pragma unroll
                for (int p = 0; p < 4; p++)
                    acc[i][p] = ffma2(ar[i], br[p], acc[i][p]);
            }
        }
        if (c + 1 < NCH) {
            const int nb = (c + 1) & 1;
            const float av[4] = {a0.x, a0.y, a0.z, a0.w};
            const float bv[4] = {b0.x, b0.y, b0.z, b0.w};
            __syncthreads();
#pragma unroll
            for (int q = 0; q < 4; q++) {
                *reinterpret_cast<ull*>(&S.As[nb][kq + q][2 * rowL]) = pack2(av[q], av[q]);
                S.Bs[nb][kq + q][rowL] = bv[q];
            }
            __syncthreads();
        }
    }

    ull bias2[4];
#pragma unroll
    for (int p = 0; p < 4; p++)
        bias2[p] = *reinterpret_cast<const ull*>(&bias[n0 + tcol * 8 + 2 * p]);
#pragma unroll
    for (int i = 0; i < 8; i++) {
        int rr = m0 + trow * 8 + i;
        int t2 = rr >> 5, b2 = rr & 31;
        size_t base = (((size_t)dir * TT + t2) * BB + b2) * GG + n0 + tcol * 8;
#pragma unroll
        for (int p = 0; p < 4; p++)
            *reinterpret_cast<ull*>(&d_pre[base + 2 * p]) = fadd2(acc[i][p], bias2[p]);
    }

    // publish: tile (dir, tg) done
    __syncthreads();
    if (tid == 0) {
        unsigned* pc = &d_pcnt[dir * 128 + tg];
        asm volatile("red.release.gpu.global.add.u32 [%0],%1;" :: "l"(pc), "r"(1u) : "memory");
    }
}

// ---------------- LSTM role: persistent recurrence block ------------------
__device__ __forceinline__ void lstm_role(int bid, LstmS& S,
    const float* __restrict__ Whf, const float* __restrict__ Whb)
{
    const int g = bid >> 3;         // group 0..15 : dir = g>>3, bg = g&7
    const int jc = bid & 7;
    const int dir = g >> 3;
    const int bg = g & 7;
    const float* __restrict__ Whh = dir ? Whb : Whf;
    const int tid = threadIdx.x;
    const int jj = tid >> 3;
    const int kc = tid & 7;
    const int j = jc * 32 + jj;
    unsigned* cnt = &d_cnt[g * 32];

    float w[4][32];
#pragma unroll
    for (int gg = 0; gg < 4; gg++)
#pragma unroll
        for (int kk = 0; kk < 32; kk++)
            w[gg][kk] = __ldg(&Whh[(size_t)(gg * HH + j) * HH + (kk * 8 + kc)]);

    float cst[4] = {0.f, 0.f, 0.f, 0.f};

    // zero initial h (this block's j-slice for its 4 batches), then release-add
    if (kc == 0) {
#pragma unroll
        for (int b = 0; b < 4; b++)
            __stcg(&d_hbuf[((0 * 2 + dir) * BB + bg * 4 + b) * HH + j], 0.f);
    }
    __syncthreads();
    if (tid == 0)
        asm volatile("red.release.gpu.global.add.u32 [%0],%1;" :: "l"(cnt), "r"(1u) : "memory");

    for (int t = 0; t < TT; t++) {
        const int par = t & 1;
        if (tid == 0) {
            unsigned v;
            if ((t & 3) == 0) {           // gate on pre tile for this 4-step window
                unsigned* pc = &d_pcnt[dir * 128 + (t >> 2)];
                do {
                    asm volatile("ld.acquire.gpu.global.u32 %0,[%1];" : "=r"(v) : "l"(pc));
                } while (v < 8u);
            }
            const unsigned target = 8u * (unsigned)(t + 1);
            do {
                asm volatile("ld.acquire.gpu.global.u32 %0,[%1];" : "=r"(v) : "l"(cnt));
            } while (v < target);
        }
        __syncthreads();

        float pv0, pv1, hv[4];
        {
            size_t pbase = (((size_t)dir * TT + t) * BB + bg * 4) * GG;
            int i0 = tid, i1 = tid + 256;
            pv0 = __ldcg(&d_pre[pbase + (size_t)((i0 >> 5) & 3) * GG + (i0 >> 7) * HH + jc * 32 + (i0 & 31)]);
            pv1 = __ldcg(&d_pre[pbase + (size_t)((i1 >> 5) & 3) * GG + (i1 >> 7) * HH + jc * 32 + (i1 & 31)]);
        }
#pragma unroll
        for (int q = 0; q < 4; q++) {
            int i = tid + q * 256;
            int b = i >> 8, k = i & 255;
            hv[q] = __ldcg(&d_hbuf[((par * 2 + dir) * BB + bg * 4 + b) * HH + k]);
        }
        S.pre_s[par][tid] = pv0;
        S.pre_s[par][tid + 256] = pv1;
#pragma unroll
        for (int q = 0; q < 4; q++) {
            int i = tid + q * 256;
            S.h_s[par][i & 255][i >> 8] = hv[q];
        }
        __syncthreads();

        ull acc[4][2];
#pragma unroll
        for (int gg = 0; gg < 4; gg++) { acc[gg][0] = 0ull; acc[gg][1] = 0ull; }
#pragma unroll
        for (int kk = 0; kk < 32; kk++) {
            int k = kk * 8 + kc;
            ull hp0 = *reinterpret_cast<const ull*>(&S.h_s[par][k][0]);
            ull hp1 = *reinterpret_cast<const ull*>(&S.h_s[par][k][2]);
#pragma unroll
            for (int gg = 0; gg < 4; gg++) {
                ull wd = pack2(w[gg][kk], w[gg][kk]);
                acc[gg][0] = ffma2(wd, hp0, acc[gg][0]);
                acc[gg][1] = ffma2(wd, hp1, acc[gg][1]);
            }
        }
        float s[4][4];
#pragma unroll
        for (int gg = 0; gg < 4; gg++) {
            unpack2(acc[gg][0], s[gg][0], s[gg][1]);
            unpack2(acc[gg][1], s[gg][2], s[gg][3]);
        }
#pragma unroll
        for (int d = 1; d < 8; d <<= 1)
#pragma unroll
            for (int gg = 0; gg < 4; gg++)
#pragma unroll
                for (int b = 0; b < 4; b++)
                    s[gg][b] += __shfl_xor_sync(0xffffffffu, s[gg][b], d);

        if (kc == 0) {
#pragma unroll
            for (int b = 0; b < 4; b++) {
                float gi = s[0][b] + S.pre_s[par][0 * 128 + b * 32 + jj];
                float gf = s[1][b] + S.pre_s[par][1 * 128 + b * 32 + jj];
                float gg2 = s[2][b] + S.pre_s[par][2 * 128 + b * 32 + jj];
                float go = s[3][b] + S.pre_s[par][3 * 128 + b * 32 + jj];
                float c = sigmoidf_(gf) * cst[b] + sigmoidf_(gi) * tanhf(gg2);
                cst[b] = c;
                float h = sigmoidf_(go) * tanhf(c);
                int gb = bg * 4 + b;
                __stcg(&d_hbuf[(((par ^ 1) * 2 + dir) * BB + gb) * HH + j], h);
                d_hall[(((size_t)dir * TT + t) * BB + gb) * HH + j] = h;
            }
        }
        __syncthreads();
        if (tid == 0)
            asm volatile("red.release.gpu.global.add.u32 [%0],%1;" :: "l"(cnt), "r"(1u) : "memory");
    }
}

// ============ K1: fused GEMM + LSTM (overlapped via counters) =============
__global__ void __launch_bounds__(256, 2) k_fused(
    const float* __restrict__ x, const int* __restrict__ lengths,
    const float* __restrict__ Wf, const float* __restrict__ bf_,
    const float* __restrict__ Wb, const float* __restrict__ bb_,
    const float* __restrict__ Whf, const float* __restrict__ Whb)
{
    __shared__ __align__(16) SmemU sm;
    if (blockIdx.x < 128) {
        lstm_role(blockIdx.x, sm.l, Whf, Whb);
    } else {
        gemm_role(blockIdx.x - 128, sm.g, x, lengths, Wf, bf_, Wb, bb_);
    }
}

// ============ K3: emissions (W_clf register-resident, FFMA2) ==============
__global__ void __launch_bounds__(256) k_emis(
    const int* __restrict__ lengths,
    const float* __restrict__ Wclf, const float* __restrict__ bclf)
{
    const int b = blockIdx.x;
    const int tc = blockIdx.y;
    const int tid = threadIdx.x;
    const int k = tid >> 3;
    const int c8 = tid & 7;
    const int L = __ldg(&lengths[b]);

    ull wreg[32];
#pragma unroll
    for (int q = 0; q < 32; q++) {
        int p = q * 8 + c8;
        wreg[q] = pack2(__ldg(&Wclf[(size_t)k * 512 + 2 * p]),
                        __ldg(&Wclf[(size_t)k * 512 + 2 * p + 1]));
    }
    const float bias = __ldg(&bclf[k]);

    __shared__ float hs[2][512];

    auto load_row = [&](int t, float& v0, float& v1) {
        v0 = d_hall[(((size_t)0 * TT + t) * BB + b) * HH + tid];
        int st = (t < L) ? (L - 1 - t) : t;
        v1 = d_hall[(((size_t)1 * TT + st) * BB + b) * HH + tid];
    };

    float v0, v1;
    load_row(tc * 256, v0, v1);
    for (int tt = 0; tt < 256; tt++) {
        const int t = tc * 256 + tt;
        const int par = tt & 1;
        hs[par][tid] = v0;
        hs[par][tid + 256] = v1;
        __syncthreads();
        if (tt + 1 < 256) load_row(t + 1, v0, v1);

        ull acc = 0ull;
#pragma unroll
        for (int q = 0; q < 32; q++) {
            int p = q * 8 + c8;
            acc = ffma2(wreg[q], *reinterpret_cast<const ull*>(&hs[par][2 * p]), acc);
        }
        float lo, hi;
        unpack2(acc, lo, hi);
        float tot = lo + hi;
#pragma unroll
        for (int d = 1; d < 8; d <<= 1)
            tot += __shfl_xor_sync(0xffffffffu, tot, d);
        if (c8 == 0)
            d_em[((size_t)b * TT + t) * KK + k] = tot + bias;
    }
}

// ---------------- warp float max via REDUX (order-preserving int map) -----
__device__ __forceinline__ float warp_max32(float x) {
    int k = __float_as_int(x);
    k = (k >= 0) ? k : (k ^ 0x7fffffff);
    int m = __reduce_max_sync(0xffffffffu, k);
    m = (m >= 0) ? m : (m ^ 0x7fffffff);
    return __int_as_float(m);
}

// ============ K4: CRF forward + Viterbi — smem-broadcast, tree reduce =====
__global__ void __launch_bounds__(64) k_crf(
    const int* __restrict__ lengths, const int* __restrict__ targets,
    const float* __restrict__ st, const float* __restrict__ en,
    const float* __restrict__ trans)
{
    const int b = blockIdx.x;
    const int wid = threadIdx.x >> 5;
    const int j = threadIdx.x & 31;
    const int L = __ldg(&lengths[b]);
    float e0 = __ldg(&d_em[((size_t)b * TT + 0) * KK + j]);

    __shared__ __align__(16) float ea_s[32];
    __shared__ __align__(16) float sc_s[32];

    if (wid == 0) {
        // lse_i(alpha_i + tr_ij) = m + log(sum_i exp(alpha_i - m) * exp(tr_ij))
        float etr[32];
#pragma unroll
        for (int i = 0; i < 32; i++) etr[i] = __expf(__ldg(&trans[i * 32 + j]));
        float alpha = __ldg(&st[j]) + e0;
        float e = (L > 1) ? __ldg(&d_em[((size_t)b * TT + 1) * KK + j]) : 0.f;
        for (int t = 1; t < L; t++) {
            float e_cur = e;
            if (t + 1 < L) e = __ldg(&d_em[((size_t)b * TT + t + 1) * KK + j]);
            float m = warp_max32(alpha);
            float ea = __expf(alpha - m);
            ea_s[j] = ea;
            __syncwarp();
            float ev[32];
#pragma unroll
            for (int q = 0; q < 8; q++) {
                float4 v4 = *reinterpret_cast<const float4*>(&ea_s[q * 4]);
                ev[q * 4 + 0] = v4.x; ev[q * 4 + 1] = v4.y;
                ev[q * 4 + 2] = v4.z; ev[q * 4 + 3] = v4.w;
            }
            __syncwarp();
            float s0 = 0.f, s1 = 0.f, s2 = 0.f, s3 = 0.f;
#pragma unroll
            for (int i = 0; i < 32; i += 4) {
                s0 = fmaf(ev[i + 0], etr[i + 0], s0);
                s1 = fmaf(ev[i + 1], etr[i + 1], s1);
                s2 = fmaf(ev[i + 2], etr[i + 2], s2);
                s3 = fmaf(ev[i + 3], etr[i + 3], s3);
            }
            alpha = m + __logf((s0 + s1) + (s2 + s3)) + e_cur;
        }
        float a = alpha + __ldg(&en[j]);
        float m2 = warp_max32(a);
        float ssum2 = __expf(a - m2);
#pragma unroll
        for (int o = 16; o; o >>= 1) ssum2 += __shfl_xor_sync(0xffffffffu, ssum2, o);
        float logZ = m2 + __logf(ssum2);
        float np = 0.f;
        for (int t = 1 + j; t < L; t += 32) {
            int pt = __ldg(&targets[b * TT + t - 1]);
            int ct = __ldg(&targets[b * TT + t]);
            np += __ldg(&trans[pt * 32 + ct]) + __ldg(&d_em[((size_t)b * TT + t) * KK + ct]);
        }
#pragma unroll
        for (int o = 16; o; o >>= 1) np += __shfl_xor_sync(0xffffffffu, np, o);
        if (j == 0) {
            int tg0 = __ldg(&targets[b * TT + 0]);
            int tgl = __ldg(&targets[b * TT + L - 1]);
            float num = __ldg(&st[tg0]) + __ldg(&d_em[((size_t)b * TT) * KK + tg0]) + np + __ldg(&en[tgl]);
            d_nll[b] = num - logZ;
        }
    } else {
        float trj[32];
#pragma unroll
        for (int i = 0; i < 32; i++) trj[i] = __ldg(&trans[i * 32 + j]);
        float sc = __ldg(&st[j]) + e0;
        float e = (L > 1) ? __ldg(&d_em[((size_t)b * TT + 1) * KK + j]) : 0.f;
        for (int t = 1; t < L; t++) {
            float e_cur = e;
            if (t + 1 < L) e = __ldg(&d_em[((size_t)b * TT + t + 1) * KK + j]);
            sc_s[j] = sc;
            __syncwarp();
            float v[32];
#pragma unroll
            for (int q = 0; q < 8; q++) {
                float4 v4 = *reinterpret_cast<const float4*>(&sc_s[q * 4]);
                v[q * 4 + 0] = v4.x + trj[q * 4 + 0];
                v[q * 4 + 1] = v4.y + trj[q * 4 + 1];
                v[q * 4 + 2] = v4.z + trj[q * 4 + 2];
                v[q * 4 + 3] = v4.w + trj[q * 4 + 3];
            }
            __syncwarp();
            // depth-5 tournament, left (lower index) wins ties -> first argmax
            float tv[16]; int ti[16];
#pragma unroll
            for (int i = 0; i < 16; i++) {
                bool sw = v[2 * i + 1] > v[2 * i];
                tv[i] = sw ? v[2 * i + 1] : v[2 * i];
                ti[i] = sw ? (2 * i + 1) : (2 * i);
            }
#pragma unroll
            for (int i = 0; i < 8; i++) {
                bool sw = tv[2 * i + 1] > tv[2 * i];
                tv[i] = sw ? tv[2 * i + 1] : tv[2 * i];
                ti[i] = sw ? ti[2 * i + 1] : ti[2 * i];
            }
#pragma unroll
            for (int i = 0; i < 4; i++) {
                bool sw = tv[2 * i + 1] > tv[2 * i];
                tv[i] = sw ? tv[2 * i + 1] : tv[2 * i];
                ti[i] = sw ? ti[2 * i + 1] : ti[2 * i];
            }
#pragma unroll
            for (int i = 0; i < 2; i++) {
                bool sw = tv[2 * i + 1] > tv[2 * i];
                tv[i] = sw ? tv[2 * i + 1] : tv[2 * i];
                ti[i] = sw ? ti[2 * i + 1] : ti[2 * i];
            }
            bool sw = tv[1] > tv[0];
            float bm = sw ? tv[1] : tv[0];
            int bi = sw ? ti[1] : ti[0];
            d_hist[((size_t)b * 511 + (t - 1)) * KK + j] = (unsigned char)bi;
            sc = bm + e_cur;
        }
        float bm = sc + __ldg(&en[j]);
        int bi = j;
#pragma unroll
        for (int o = 16; o; o >>= 1) {
            float om = __shfl_xor_sync(0xffffffffu, bm, o);
            int oi = __shfl_xor_sync(0xffffffffu, bi, o);
            if (om > bm || (om == bm && oi < bi)) { bm = om; bi = oi; }
        }
        if (j == 0) d_last[b] = bi;
    }
}

// ============ K5: backtrack (smem-staged hist) + loss =====================
__global__ void __launch_bounds__(128) k_back(
    const int* __restrict__ lengths, float* __restrict__ out, int out_size)
{
    const int b = blockIdx.x;
    const int tid = threadIdx.x;
    const bool has_loss = (out_size >= BB * TT + 1);
    const int off = has_loss ? 1 : 0;
    if (out_size < BB * TT) {
        if (b == 0 && tid == 0 && out_size >= 1) {
            float acc = 0.f;
            for (int q = 0; q < BB; q++) acc += d_nll[q];
            out[0] = -acc / (float)BB;
        }
        return;
    }
    __shared__ __align__(16) unsigned char hist_s[511 * KK];
    __shared__ int path[TT];
    {
        const int4* src = reinterpret_cast<const int4*>(&d_hist[(size_t)b * 511 * KK]);
        int4* dst = reinterpret_cast<int4*>(hist_s);
        for (int i = tid; i < (511 * KK) / 16; i += 128) dst[i] = src[i];
    }
    __syncthreads();
    const int L = lengths[b];
    if (tid == 0) {
        int tag = d_last[b];
        path[TT - 1] = tag;
        for (int s = TT - 2; s >= 0; s--) {
            int t = s + 1;
            int prev = (t < L) ? (int)hist_s[s * KK + tag] : tag;
            path[s] = prev;
            tag = prev;
        }
    }
    __syncthreads();
    for (int s = tid; s < TT; s += 128)
        out[off + b * TT + s] = (s < L) ? (float)path[s] : 0.f;
    if (b == 0 && tid == 0 && has_loss) {
        float acc = 0.f;
        for (int q = 0; q < BB; q++) acc += d_nll[q];
        out[0] = -acc / (float)BB;
    }
}

// ---------------- launch ----------------
extern "C" void kernel_launch(void* const* d_in, const int* in_sizes, int n_in,
                              void* d_out, int out_size)
{
    const float* x      = (const float*)d_in[0];
    const int* lengths  = (const int*)d_in[1];
    const int* targets  = (const int*)d_in[3];
    const float* Wihf   = (const float*)d_in[4];
    const float* Whhf   = (const float*)d_in[5];
    const float* bf_    = (const float*)d_in[6];
    const float* Wihb   = (const float*)d_in[7];
    const float* Whhb   = (const float*)d_in[8];
    const float* bb_    = (const float*)d_in[9];
    const float* Wclf   = (const float*)d_in[10];
    const float* bclf   = (const float*)d_in[11];
    const float* st     = (const float*)d_in[12];
    const float* en     = (const float*)d_in[13];
    const float* tr     = (const float*)d_in[14];

    k_init<<<1, 256>>>();
    k_fused<<<128 + 2048, 256>>>(x, lengths, Wihf, bf_, Wihb, bb_, Whhf, Whhb);
    k_emis<<<dim3(32, 2), 256>>>(lengths, Wclf, bclf);
    k_crf<<<32, 64>>>(lengths, targets, st, en, tr);
    k_back<<<32, 128>>>(lengths, (float*)d_out, out_size);
}

// round 11
// speedup vs baseline: 1.8114x; 1.0323x over previous
#include <cuda_runtime.h>
#include <cuda_bf16.h>
#include <mma.h>
#include <math.h>

using namespace nvcuda;

#define TT 512
#define BB 32
#define DD 768
#define HH 256
#define GG 1024   // 4*H
#define KK 32
#define NKC 48    // 768/16 k-chunks

typedef unsigned long long ull;

// ---------------- packed f32x2 helpers ----------------
__device__ __forceinline__ ull pack2(float x, float y) {
    ull r; asm("mov.b64 %0,{%1,%2};" : "=l"(r) : "f"(x), "f"(y)); return r;
}
__device__ __forceinline__ void unpack2(ull v, float& x, float& y) {
    asm("mov.b64 {%0,%1},%2;" : "=f"(x), "=f"(y) : "l"(v));
}
__device__ __forceinline__ ull ffma2(ull a, ull b, ull c) {
    ull d; asm("fma.rn.f32x2 %0,%1,%2,%3;" : "=l"(d) : "l"(a), "l"(b), "l"(c)); return d;
}

// ---------------- device scratch ----------------
__device__ float d_pre[(size_t)2 * TT * BB * GG];      // [dir][m][4H]  (m = t*32+b)
__device__ float d_hall[(size_t)2 * TT * BB * HH];
__device__ float d_hbuf[2 * 2 * BB * HH];
__device__ float d_em[(size_t)BB * TT * KK];
__device__ unsigned char d_hist[(size_t)BB * 511 * KK];
__device__ float d_nll[BB];
__device__ int d_last[BB];
__device__ unsigned d_cnt[16 * 32];
__device__ unsigned d_pcnt[2 * 128];
// split bf16 operands: A planes [ (dir*3+s)*48 + kc ][ m(16384) ][16]
__device__ __nv_bfloat16 d_ax[(size_t)2 * 3 * NKC * 16384 * 16];
// B planes: [ (dir*3+s)*48 + kc ][ n(1024) ][16]
__device__ __nv_bfloat16 d_bw[(size_t)2 * 3 * NKC * 1024 * 16];

__device__ __forceinline__ float sigmoidf_(float v) { return 1.f / (1.f + __expf(-v)); }

// ============ K0: reset counters ===========
__global__ void k_init()
{
    int i = threadIdx.x;
    if (i < 2 * 128) d_pcnt[i] = 0;
    for (int q = i; q < 16 * 32; q += 256) d_cnt[q] = 0;
}

// ============ K0b: split x and W into 3-component bf16 planes =============
__global__ void __launch_bounds__(256) k_split(
    const float* __restrict__ x, const int* __restrict__ lengths,
    const float* __restrict__ Wf, const float* __restrict__ Wb)
{
    const unsigned u = blockIdx.x * 256 + threadIdx.x;
    const unsigned NA = 2u * NKC * 16384;   // A tasks
    const float* src;
    size_t plane_row;           // row index within plane group; plane stride differs A/B
    bool isA;
    unsigned dir, kc;
    if (u < NA) {
        isA = true;
        unsigned m = u & 16383u;
        unsigned q = u >> 14;
        kc = q % NKC; dir = q / NKC;
        int t = m >> 5, b = m & 31;
        int st = t;
        if (dir) { int L = __ldg(&lengths[b]); st = (t < L) ? (L - 1 - t) : t; }
        src = x + ((size_t)b * TT + st) * DD + kc * 16;
        plane_row = m;
    } else {
        isA = false;
        unsigned v = u - NA;
        unsigned n = v & 1023u;
        unsigned q = v >> 10;
        kc = q % NKC; dir = q / NKC;
        const float* W = dir ? Wb : Wf;
        src = W + (size_t)n * DD + kc * 16;
        plane_row = n;
    }
    unsigned hw[8], mw[8], lw[8];
#pragma unroll
    for (int i = 0; i < 8; i++) {
        unsigned short hh[2], mm2[2], ll[2];
#pragma unroll
        for (int p = 0; p < 2; p++) {
            float xv = __ldg(&src[i * 2 + p]);
            __nv_bfloat16 bh = __float2bfloat16_rn(xv);
            float r1 = xv - __bfloat162float(bh);
            __nv_bfloat16 bm = __float2bfloat16_rn(r1);
            float r2 = r1 - __bfloat162float(bm);
            __nv_bfloat16 bl = __float2bfloat16_rn(r2);
            hh[p] = __bfloat16_as_ushort(bh);
            mm2[p] = __bfloat16_as_ushort(bm);
            ll[p] = __bfloat16_as_ushort(bl);
        }
        hw[i] = (unsigned)hh[0] | ((unsigned)hh[1] << 16);
        mw[i] = (unsigned)mm2[0] | ((unsigned)mm2[1] << 16);
        lw[i] = (unsigned)ll[0] | ((unsigned)ll[1] << 16);
    }
    if (isA) {
#pragma unroll
        for (int s = 0; s < 3; s++) {
            size_t plane = (size_t)(dir * 3 + s) * NKC + kc;
            uint4* dst = reinterpret_cast<uint4*>(d_ax + (plane * 16384 + plane_row) * 16);
            const unsigned* w = (s == 0) ? hw : (s == 1) ? mw : lw;
            dst[0] = make_uint4(w[0], w[1], w[2], w[3]);
            dst[1] = make_uint4(w[4], w[5], w[6], w[7]);
        }
    } else {
#pragma unroll
        for (int s = 0; s < 3; s++) {
            size_t plane = (size_t)(dir * 3 + s) * NKC + kc;
            uint4* dst = reinterpret_cast<uint4*>(d_bw + (plane * 1024 + plane_row) * 16);
            const unsigned* w = (s == 0) ? hw : (s == 1) ? mw : lw;
            dst[0] = make_uint4(w[0], w[1], w[2], w[3]);
            dst[1] = make_uint4(w[4], w[5], w[6], w[7]);
        }
    }
}

// ---------------- GEMM role: wmma bf16 128x128 tile -----------------------
// dyn smem: A bufs [2][3][128*16] bf16 then B bufs [2][3][128*16]: 48KB
#define ABUF(sm, cb, s) (reinterpret_cast<__nv_bfloat16*>((sm) + ((cb) * 6 + (s)) * 4096))
#define BBUF(sm, cb, s) (reinterpret_cast<__nv_bfloat16*>((sm) + ((cb) * 6 + 3 + (s)) * 4096))

__device__ void gemm_role(int gbid, char* sm)
{
    const int tg  = gbid >> 4;
    const int sub = gbid & 15;
    const int dir = sub >> 3;
    const int n0  = (sub & 7) * 128;
    const int m0  = tg * 128;
    const int tid = threadIdx.x;
    const int wid = tid >> 5;
    const int warp_m = (wid >> 2) * 64;   // 0 or 64
    const int warp_n = (wid & 3) * 32;    // 0,32,64,96

    wmma::fragment<wmma::accumulator, 16, 16, 16, float> ac[4][2];
#pragma unroll
    for (int i = 0; i < 4; i++)
#pragma unroll
        for (int jj = 0; jj < 2; jj++)
            wmma::fill_fragment(ac[i][jj], 0.0f);

    uint4 rA[3], rB[3];
    auto load_regs = [&](int kc) {
#pragma unroll
        for (int s = 0; s < 3; s++) {
            size_t pa = (size_t)(dir * 3 + s) * NKC + kc;
            rA[s] = reinterpret_cast<const uint4*>(d_ax)[(pa * 16384 + m0) * 2 + tid];
            rB[s] = reinterpret_cast<const uint4*>(d_bw)[(pa * 1024 + n0) * 2 + tid];
        }
    };
    auto store_regs = [&](int cb) {
#pragma unroll
        for (int s = 0; s < 3; s++) {
            reinterpret_cast<uint4*>(ABUF(sm, cb, s))[tid] = rA[s];
            reinterpret_cast<uint4*>(BBUF(sm, cb, s))[tid] = rB[s];
        }
    };

    load_regs(0);
    store_regs(0);
    __syncthreads();

    // term table: pa -> list of pb
    for (int c = 0; c < NKC; c++) {
        const int cb = c & 1;
        if (c + 1 < NKC) load_regs(c + 1);

        wmma::fragment<wmma::matrix_a, 16, 16, 16, __nv_bfloat16, wmma::row_major> af[4];
        wmma::fragment<wmma::matrix_b, 16, 16, 16, __nv_bfloat16, wmma::col_major> bfr[2];
#pragma unroll
        for (int pa = 0; pa < 3; pa++) {
            const __nv_bfloat16* Ab = ABUF(sm, cb, pa);
#pragma unroll
            for (int i = 0; i < 4; i++)
                wmma::load_matrix_sync(af[i], Ab + (warp_m + i * 16) * 16, 16);
            const int npb = (pa == 0) ? 3 : (pa == 1) ? 2 : 1;
#pragma unroll
            for (int pb = 0; pb < 3; pb++) {
                if (pb >= npb) break;
                const __nv_bfloat16* Bb = BBUF(sm, cb, pb);
#pragma unroll
                for (int jj = 0; jj < 2; jj++)
                    wmma::load_matrix_sync(bfr[jj], Bb + (warp_n + jj * 16) * 16, 16);
#pragma unroll
                for (int i = 0; i < 4; i++)
#pragma unroll
                    for (int jj = 0; jj < 2; jj++)
                        wmma::mma_sync(ac[i][jj], af[i], bfr[jj], ac[i][jj]);
            }
        }
        __syncthreads();
        if (c + 1 < NKC) {
            store_regs((c + 1) & 1);
            __syncthreads();
        }
    }

    // epilogue: store accumulators straight to d_pre (bias added in LSTM role)
    float* dstbase = d_pre + ((size_t)dir * 16384 + m0) * GG + n0;
#pragma unroll
    for (int i = 0; i < 4; i++)
#pragma unroll
        for (int jj = 0; jj < 2; jj++)
            wmma::store_matrix_sync(
                dstbase + (size_t)(warp_m + i * 16) * GG + warp_n + jj * 16,
                ac[i][jj], GG, wmma::mem_row_major);

    __syncthreads();
    if (tid == 0) {
        unsigned* pc = &d_pcnt[dir * 128 + tg];
        asm volatile("red.release.gpu.global.add.u32 [%0],%1;" :: "l"(pc), "r"(1u) : "memory");
    }
}

// ---------------- LSTM role: persistent recurrence block ------------------
struct LstmS {
    float h_s[2][HH][4];
    float pre_s[2][512];
};

__device__ void lstm_role(int bid, LstmS& S,
    const float* __restrict__ Whf, const float* __restrict__ Whb,
    const float* __restrict__ bf_, const float* __restrict__ bb_)
{
    const int g = bid >> 3;
    const int jc = bid & 7;
    const int dir = g >> 3;
    const int bg = g & 7;
    const float* __restrict__ Whh = dir ? Whb : Whf;
    const float* __restrict__ bias = dir ? bb_ : bf_;
    const int tid = threadIdx.x;
    const int jj = tid >> 3;
    const int kc = tid & 7;
    const int j = jc * 32 + jj;
    unsigned* cnt = &d_cnt[g * 32];

    float w[4][32];
#pragma unroll
    for (int gg = 0; gg < 4; gg++)
#pragma unroll
        for (int kk = 0; kk < 32; kk++)
            w[gg][kk] = __ldg(&Whh[(size_t)(gg * HH + j) * HH + (kk * 8 + kc)]);

    // bias for this thread's two pre elements (gate = i>>7)
    const float bv0 = __ldg(&bias[(tid >> 7) * HH + jc * 32 + (tid & 31)]);
    const float bv1 = __ldg(&bias[((tid >> 7) + 2) * HH + jc * 32 + (tid & 31)]);

    float cst[4] = {0.f, 0.f, 0.f, 0.f};

    if (kc == 0) {
#pragma unroll
        for (int b = 0; b < 4; b++)
            __stcg(&d_hbuf[((0 * 2 + dir) * BB + bg * 4 + b) * HH + j], 0.f);
    }
    __syncthreads();
    if (tid == 0)
        asm volatile("red.release.gpu.global.add.u32 [%0],%1;" :: "l"(cnt), "r"(1u) : "memory");

    for (int t = 0; t < TT; t++) {
        const int par = t & 1;
        if (tid == 0) {
            unsigned v;
            if ((t & 3) == 0) {
                unsigned* pc = &d_pcnt[dir * 128 + (t >> 2)];
                do {
                    asm volatile("ld.acquire.gpu.global.u32 %0,[%1];" : "=r"(v) : "l"(pc));
                } while (v < 8u);
            }
            const unsigned target = 8u * (unsigned)(t + 1);
            do {
                asm volatile("ld.acquire.gpu.global.u32 %0,[%1];" : "=r"(v) : "l"(cnt));
            } while (v < target);
        }
        __syncthreads();

        float pv0, pv1, hv[4];
        {
            size_t pbase = (((size_t)dir * TT + t) * BB + bg * 4) * GG;
            int i0 = tid, i1 = tid + 256;
            pv0 = __ldcg(&d_pre[pbase + (size_t)((i0 >> 5) & 3) * GG + (i0 >> 7) * HH + jc * 32 + (i0 & 31)]) + bv0;
            pv1 = __ldcg(&d_pre[pbase + (size_t)((i1 >> 5) & 3) * GG + (i1 >> 7) * HH + jc * 32 + (i1 & 31)]) + bv1;
        }
#pragma unroll
        for (int q = 0; q < 4; q++) {
            int i = tid + q * 256;
            int b = i >> 8, k = i & 255;
            hv[q] = __ldcg(&d_hbuf[((par * 2 + dir) * BB + bg * 4 + b) * HH + k]);
        }
        S.pre_s[par][tid] = pv0;
        S.pre_s[par][tid + 256] = pv1;
#pragma unroll
        for (int q = 0; q < 4; q++) {
            int i = tid + q * 256;
            S.h_s[par][i & 255][i >> 8] = hv[q];
        }
        __syncthreads();

        ull acc[4][2];
#pragma unroll
        for (int gg = 0; gg < 4; gg++) { acc[gg][0] = 0ull; acc[gg][1] = 0ull; }
#pragma unroll
        for (int kk = 0; kk < 32; kk++) {
            int k = kk * 8 + kc;
            ull hp0 = *reinterpret_cast<const ull*>(&S.h_s[par][k][0]);
            ull hp1 = *reinterpret_cast<const ull*>(&S.h_s[par][k][2]);
#pragma unroll
            for (int gg = 0; gg < 4; gg++) {
                ull wd = pack2(w[gg][kk], w[gg][kk]);
                acc[gg][0] = ffma2(wd, hp0, acc[gg][0]);
                acc[gg][1] = ffma2(wd, hp1, acc[gg][1]);
            }
        }
        float s[4][4];
#pragma unroll
        for (int gg = 0; gg < 4; gg++) {
            unpack2(acc[gg][0], s[gg][0], s[gg][1]);
            unpack2(acc[gg][1], s[gg][2], s[gg][3]);
        }
#pragma unroll
        for (int d = 1; d < 8; d <<= 1)
#pragma unroll
            for (int gg = 0; gg < 4; gg++)
#pragma unroll
                for (int b = 0; b < 4; b++)
                    s[gg][b] += __shfl_xor_sync(0xffffffffu, s[gg][b], d);

        if (kc == 0) {
#pragma unroll
            for (int b = 0; b < 4; b++) {
                float gi = s[0][b] + S.pre_s[par][0 * 128 + b * 32 + jj];
                float gf = s[1][b] + S.pre_s[par][1 * 128 + b * 32 + jj];
                float gg2 = s[2][b] + S.pre_s[par][2 * 128 + b * 32 + jj];
                float go = s[3][b] + S.pre_s[par][3 * 128 + b * 32 + jj];
                float c = sigmoidf_(gf) * cst[b] + sigmoidf_(gi) * tanhf(gg2);
                cst[b] = c;
                float h = sigmoidf_(go) * tanhf(c);
                int gb = bg * 4 + b;
                __stcg(&d_hbuf[(((par ^ 1) * 2 + dir) * BB + gb) * HH + j], h);
                d_hall[(((size_t)dir * TT + t) * BB + gb) * HH + j] = h;
            }
        }
        __syncthreads();
        if (tid == 0)
            asm volatile("red.release.gpu.global.add.u32 [%0],%1;" :: "l"(cnt), "r"(1u) : "memory");
    }
}

// ============ K1: fused wmma-GEMM + LSTM =============
__global__ void __launch_bounds__(256, 2) k_fused(
    const float* __restrict__ Whf, const float* __restrict__ Whb,
    const float* __restrict__ bf_, const float* __restrict__ bb_)
{
    extern __shared__ __align__(256) char sm[];
    if (blockIdx.x < 128) {
        lstm_role(blockIdx.x, *reinterpret_cast<LstmS*>(sm), Whf, Whb, bf_, bb_);
    } else {
        gemm_role(blockIdx.x - 128, sm);
    }
}

// ============ K3: emissions (W_clf register-resident, FFMA2) ==============
__global__ void __launch_bounds__(256) k_emis(
    const int* __restrict__ lengths,
    const float* __restrict__ Wclf, const float* __restrict__ bclf)
{
    const int b = blockIdx.x;
    const int tc = blockIdx.y;
    const int tid = threadIdx.x;
    const int k = tid >> 3;
    const int c8 = tid & 7;
    const int L = __ldg(&lengths[b]);

    ull wreg[32];
#pragma unroll
    for (int q = 0; q < 32; q++) {
        int p = q * 8 + c8;
        wreg[q] = pack2(__ldg(&Wclf[(size_t)k * 512 + 2 * p]),
                        __ldg(&Wclf[(size_t)k * 512 + 2 * p + 1]));
    }
    const float bias = __ldg(&bclf[k]);

    __shared__ float hs[2][512];

    auto load_row = [&](int t, float& v0, float& v1) {
        v0 = d_hall[(((size_t)0 * TT + t) * BB + b) * HH + tid];
        int st = (t < L) ? (L - 1 - t) : t;
        v1 = d_hall[(((size_t)1 * TT + st) * BB + b) * HH + tid];
    };

    float v0, v1;
    load_row(tc * 256, v0, v1);
    for (int tt = 0; tt < 256; tt++) {
        const int t = tc * 256 + tt;
        const int par = tt & 1;
        hs[par][tid] = v0;
        hs[par][tid + 256] = v1;
        __syncthreads();
        if (tt + 1 < 256) load_row(t + 1, v0, v1);

        ull acc = 0ull;
#pragma unroll
        for (int q = 0; q < 32; q++) {
            int p = q * 8 + c8;
            acc = ffma2(wreg[q], *reinterpret_cast<const ull*>(&hs[par][2 * p]), acc);
        }
        float lo, hi;
        unpack2(acc, lo, hi);
        float tot = lo + hi;
#pragma unroll
        for (int d = 1; d < 8; d <<= 1)
            tot += __shfl_xor_sync(0xffffffffu, tot, d);
        if (c8 == 0)
            d_em[((size_t)b * TT + t) * KK + k] = tot + bias;
    }
}

// ---------------- warp float max via REDUX ----------------
__device__ __forceinline__ float warp_max32(float x) {
    int k = __float_as_int(x);
    k = (k >= 0) ? k : (k ^ 0x7fffffff);
    int m = __reduce_max_sync(0xffffffffu, k);
    m = (m >= 0) ? m : (m ^ 0x7fffffff);
    return __int_as_float(m);
}

// ============ K4: CRF forward + Viterbi, 2 warps per batch ================
__global__ void __launch_bounds__(64) k_crf(
    const int* __restrict__ lengths, const int* __restrict__ targets,
    const float* __restrict__ st, const float* __restrict__ en,
    const float* __restrict__ trans)
{
    const int b = blockIdx.x;
    const int wid = threadIdx.x >> 5;
    const int j = threadIdx.x & 31;
    const int L = __ldg(&lengths[b]);
    float e0 = __ldg(&d_em[((size_t)b * TT + 0) * KK + j]);

    if (wid == 0) {
        float etr[32];
#pragma unroll
        for (int i = 0; i < 32; i++) etr[i] = __expf(__ldg(&trans[i * 32 + j]));
        float alpha = __ldg(&st[j]) + e0;
        float e = (L > 1) ? __ldg(&d_em[((size_t)b * TT + 1) * KK + j]) : 0.f;
        for (int t = 1; t < L; t++) {
            float e_cur = e;
            if (t + 1 < L) e = __ldg(&d_em[((size_t)b * TT + t + 1) * KK + j]);
            float m = warp_max32(alpha);
            float ea = __expf(alpha - m);
            float s0 = 0.f, s1 = 0.f, s2 = 0.f, s3 = 0.f;
#pragma unroll
            for (int i = 0; i < 32; i += 4) {
                s0 = fmaf(__shfl_sync(0xffffffffu, ea, i + 0), etr[i + 0], s0);
                s1 = fmaf(__shfl_sync(0xffffffffu, ea, i + 1), etr[i + 1], s1);
                s2 = fmaf(__shfl_sync(0xffffffffu, ea, i + 2), etr[i + 2], s2);
                s3 = fmaf(__shfl_sync(0xffffffffu, ea, i + 3), etr[i + 3], s3);
            }
            alpha = m + __logf((s0 + s1) + (s2 + s3)) + e_cur;
        }
        float a = alpha + __ldg(&en[j]);
        float m2 = warp_max32(a);
        float ssum2 = __expf(a - m2);
#pragma unroll
        for (int o = 16; o; o >>= 1) ssum2 += __shfl_xor_sync(0xffffffffu, ssum2, o);
        float logZ = m2 + __logf(ssum2);
        float np = 0.f;
        for (int t = 1 + j; t < L; t += 32) {
            int pt = __ldg(&targets[b * TT + t - 1]);
            int ct = __ldg(&targets[b * TT + t]);
            np += __ldg(&trans[pt * 32 + ct]) + __ldg(&d_em[((size_t)b * TT + t) * KK + ct]);
        }
#pragma unroll
        for (int o = 16; o; o >>= 1) np += __shfl_xor_sync(0xffffffffu, np, o);
        if (j == 0) {
            int tg0 = __ldg(&targets[b * TT + 0]);
            int tgl = __ldg(&targets[b * TT + L - 1]);
            float num = __ldg(&st[tg0]) + __ldg(&d_em[((size_t)b * TT) * KK + tg0]) + np + __ldg(&en[tgl]);
            d_nll[b] = num - logZ;
        }
    } else {
        float trj[32];
#pragma unroll
        for (int i = 0; i < 32; i++) trj[i] = __ldg(&trans[i * 32 + j]);
        float sc = __ldg(&st[j]) + e0;
        float e = (L > 1) ? __ldg(&d_em[((size_t)b * TT + 1) * KK + j]) : 0.f;
        for (int t = 1; t < L; t++) {
            float e_cur = e;
            if (t + 1 < L) e = __ldg(&d_em[((size_t)b * TT + t + 1) * KK + j]);
            float bm = -1e30f;
            int bi = 0;
#pragma unroll
            for (int i = 0; i < 32; i++) {
                float v = __shfl_sync(0xffffffffu, sc, i) + trj[i];
                bi = (v > bm) ? i : bi;
                bm = fmaxf(bm, v);
            }
            d_hist[((size_t)b * 511 + (t - 1)) * KK + j] = (unsigned char)bi;
            sc = bm + e_cur;
        }
        float bm = sc + __ldg(&en[j]);
        int bi = j;
#pragma unroll
        for (int o = 16; o; o >>= 1) {
            float om = __shfl_xor_sync(0xffffffffu, bm, o);
            int oi = __shfl_xor_sync(0xffffffffu, bi, o);
            if (om > bm || (om == bm && oi < bi)) { bm = om; bi = oi; }
        }
        if (j == 0) d_last[b] = bi;
    }
}

// ============ K5: backtrack + loss =====================
__global__ void __launch_bounds__(128) k_back(
    const int* __restrict__ lengths, float* __restrict__ out, int out_size)
{
    const int b = blockIdx.x;
    const int tid = threadIdx.x;
    const bool has_loss = (out_size >= BB * TT + 1);
    const int off = has_loss ? 1 : 0;
    if (out_size < BB * TT) {
        if (b == 0 && tid == 0 && out_size >= 1) {
            float acc = 0.f;
            for (int q = 0; q < BB; q++) acc += d_nll[q];
            out[0] = -acc / (float)BB;
        }
        return;
    }
    __shared__ __align__(16) unsigned char hist_s[511 * KK];
    __shared__ int path[TT];
    {
        const int4* src = reinterpret_cast<const int4*>(&d_hist[(size_t)b * 511 * KK]);
        int4* dst = reinterpret_cast<int4*>(hist_s);
        for (int i = tid; i < (511 * KK) / 16; i += 128) dst[i] = src[i];
    }
    __syncthreads();
    const int L = lengths[b];
    if (tid == 0) {
        int tag = d_last[b];
        path[TT - 1] = tag;
        for (int s = TT - 2; s >= 0; s--) {
            int t = s + 1;
            int prev = (t < L) ? (int)hist_s[s * KK + tag] : tag;
            path[s] = prev;
            tag = prev;
        }
    }
    __syncthreads();
    for (int s = tid; s < TT; s += 128)
        out[off + b * TT + s] = (s < L) ? (float)path[s] : 0.f;
    if (b == 0 && tid == 0 && has_loss) {
        float acc = 0.f;
        for (int q = 0; q < BB; q++) acc += d_nll[q];
        out[0] = -acc / (float)BB;
    }
}

// ---------------- launch ----------------
extern "C" void kernel_launch(void* const* d_in, const int* in_sizes, int n_in,
                              void* d_out, int out_size)
{
    const float* x      = (const float*)d_in[0];
    const int* lengths  = (const int*)d_in[1];
    const int* targets  = (const int*)d_in[3];
    const float* Wihf   = (const float*)d_in[4];
    const float* Whhf   = (const float*)d_in[5];
    const float* bf_    = (const float*)d_in[6];
    const float* Wihb   = (const float*)d_in[7];
    const float* Whhb   = (const float*)d_in[8];
    const float* bb_    = (const float*)d_in[9];
    const float* Wclf   = (const float*)d_in[10];
    const float* bclf   = (const float*)d_in[11];
    const float* st     = (const float*)d_in[12];
    const float* en     = (const float*)d_in[13];
    const float* tr     = (const float*)d_in[14];

    static int smem_set = 0;
    if (!smem_set) {
        cudaFuncSetAttribute(k_fused, cudaFuncAttributeMaxDynamicSharedMemorySize, 49152);
        smem_set = 1;
    }

    k_init<<<1, 256>>>();
    k_split<<<6528, 256>>>(x, lengths, Wihf, Wihb);
    k_fused<<<128 + 2048, 256, 49152>>>(Whhf, Whhb, bf_, bb_);
    k_emis<<<dim3(32, 2), 256>>>(lengths, Wclf, bclf);
    k_crf<<<32, 64>>>(lengths, targets, st, en, tr);
    k_back<<<32, 128>>>(lengths, (float*)d_out, out_size);
}

// round 12
// speedup vs baseline: 1.8219x; 1.0058x over previous
#include <cuda_runtime.h>
#include <cuda_bf16.h>
#include <mma.h>
#include <math.h>

using namespace nvcuda;

#define TT 512
#define BB 32
#define DD 768
#define HH 256
#define GG 1024   // 4*H
#define KK 32
#define NKC 48    // 768/16 k-chunks

typedef unsigned long long ull;

// ---------------- packed f32x2 helpers ----------------
__device__ __forceinline__ ull pack2(float x, float y) {
    ull r; asm("mov.b64 %0,{%1,%2};" : "=l"(r) : "f"(x), "f"(y)); return r;
}
__device__ __forceinline__ void unpack2(ull v, float& x, float& y) {
    asm("mov.b64 {%0,%1},%2;" : "=f"(x), "=f"(y) : "l"(v));
}
__device__ __forceinline__ ull ffma2(ull a, ull b, ull c) {
    ull d; asm("fma.rn.f32x2 %0,%1,%2,%3;" : "=l"(d) : "l"(a), "l"(b), "l"(c)); return d;
}

// ---------------- device scratch ----------------
__device__ float d_pre[(size_t)2 * TT * BB * GG];      // [dir][m][4H]  (m = t*32+b)
__device__ float d_hall[(size_t)2 * TT * BB * HH];
__device__ float d_hbuf[2 * 2 * BB * HH];
__device__ float d_em[(size_t)BB * TT * KK];
__device__ unsigned char d_hist[(size_t)BB * 511 * KK];
__device__ float d_nll[BB];
__device__ int d_last[BB];
__device__ unsigned d_cnt[16 * 32];
__device__ unsigned d_pcnt[2 * 128];
// split bf16 operands: A planes [ (dir*3+s)*48 + kc ][ m(16384) ][16]
__device__ __nv_bfloat16 d_ax[(size_t)2 * 3 * NKC * 16384 * 16];
// B planes: [ (dir*3+s)*48 + kc ][ n(1024) ][16]
__device__ __nv_bfloat16 d_bw[(size_t)2 * 3 * NKC * 1024 * 16];

__device__ __forceinline__ float sigmoidf_(float v) { return 1.f / (1.f + __expf(-v)); }

// ============ K0: reset counters ===========
__global__ void k_init()
{
    int i = threadIdx.x;
    if (i < 2 * 128) d_pcnt[i] = 0;
    for (int q = i; q < 16 * 32; q += 256) d_cnt[q] = 0;
}

// dummy launch so k_fused is the 4th launch (ncu captures launch #4)
__global__ void k_dummy() {}

// ============ K0b: split x and W into 3-component bf16 planes =============
__global__ void __launch_bounds__(256) k_split(
    const float* __restrict__ x, const int* __restrict__ lengths,
    const float* __restrict__ Wf, const float* __restrict__ Wb)
{
    const unsigned u = blockIdx.x * 256 + threadIdx.x;
    const unsigned NA = 2u * NKC * 16384;   // A tasks
    const float* src;
    size_t plane_row;
    bool isA;
    unsigned dir, kc;
    if (u < NA) {
        isA = true;
        unsigned m = u & 16383u;
        unsigned q = u >> 14;
        kc = q % NKC; dir = q / NKC;
        int t = m >> 5, b = m & 31;
        int st = t;
        if (dir) { int L = __ldg(&lengths[b]); st = (t < L) ? (L - 1 - t) : t; }
        src = x + ((size_t)b * TT + st) * DD + kc * 16;
        plane_row = m;
    } else {
        isA = false;
        unsigned v = u - NA;
        unsigned n = v & 1023u;
        unsigned q = v >> 10;
        kc = q % NKC; dir = q / NKC;
        const float* W = dir ? Wb : Wf;
        src = W + (size_t)n * DD + kc * 16;
        plane_row = n;
    }
    unsigned hw[8], mw[8], lw[8];
#pragma unroll
    for (int i = 0; i < 8; i++) {
        unsigned short hh[2], mm2[2], ll[2];
#pragma unroll
        for (int p = 0; p < 2; p++) {
            float xv = __ldg(&src[i * 2 + p]);
            __nv_bfloat16 bh = __float2bfloat16_rn(xv);
            float r1 = xv - __bfloat162float(bh);
            __nv_bfloat16 bm = __float2bfloat16_rn(r1);
            float r2 = r1 - __bfloat162float(bm);
            __nv_bfloat16 bl = __float2bfloat16_rn(r2);
            hh[p] = __bfloat16_as_ushort(bh);
            mm2[p] = __bfloat16_as_ushort(bm);
            ll[p] = __bfloat16_as_ushort(bl);
        }
        hw[i] = (unsigned)hh[0] | ((unsigned)hh[1] << 16);
        mw[i] = (unsigned)mm2[0] | ((unsigned)mm2[1] << 16);
        lw[i] = (unsigned)ll[0] | ((unsigned)ll[1] << 16);
    }
    if (isA) {
#pragma unroll
        for (int s = 0; s < 3; s++) {
            size_t plane = (size_t)(dir * 3 + s) * NKC + kc;
            uint4* dst = reinterpret_cast<uint4*>(d_ax + (plane * 16384 + plane_row) * 16);
            const unsigned* w = (s == 0) ? hw : (s == 1) ? mw : lw;
            dst[0] = make_uint4(w[0], w[1], w[2], w[3]);
            dst[1] = make_uint4(w[4], w[5], w[6], w[7]);
        }
    } else {
#pragma unroll
        for (int s = 0; s < 3; s++) {
            size_t plane = (size_t)(dir * 3 + s) * NKC + kc;
            uint4* dst = reinterpret_cast<uint4*>(d_bw + (plane * 1024 + plane_row) * 16);
            const unsigned* w = (s == 0) ? hw : (s == 1) ? mw : lw;
            dst[0] = make_uint4(w[0], w[1], w[2], w[3]);
            dst[1] = make_uint4(w[4], w[5], w[6], w[7]);
        }
    }
}

// ---------------- GEMM role: wmma bf16 128x128 tile -----------------------
// staged rows padded to 24 elems (48B stride) -> conflict-free LDSM.
// per-plane buf = 128*24*2 = 6144B; 6 planes per cb; 2 cb = 73728B dyn smem.
#define PLANE_BYTES 6144
#define SM_DYN (2 * 6 * PLANE_BYTES)
#define ABUF(sm, cb, s) (reinterpret_cast<__nv_bfloat16*>((sm) + ((cb) * 6 + (s)) * PLANE_BYTES))
#define BBUF(sm, cb, s) (reinterpret_cast<__nv_bfloat16*>((sm) + ((cb) * 6 + 3 + (s)) * PLANE_BYTES))

__device__ void gemm_role(int gbid, char* sm)
{
    const int tg  = gbid >> 4;
    const int sub = gbid & 15;
    const int dir = sub >> 3;
    const int n0  = (sub & 7) * 128;
    const int m0  = tg * 128;
    const int tid = threadIdx.x;
    const int wid = tid >> 5;
    const int warp_m = (wid >> 2) * 64;   // 0 or 64
    const int warp_n = (wid & 3) * 32;    // 0,32,64,96

    wmma::fragment<wmma::accumulator, 16, 16, 16, float> ac[4][2];
#pragma unroll
    for (int i = 0; i < 4; i++)
#pragma unroll
        for (int jj = 0; jj < 2; jj++)
            wmma::fill_fragment(ac[i][jj], 0.0f);

    uint4 rA[3], rB[3];
    auto load_regs = [&](int kc) {
#pragma unroll
        for (int s = 0; s < 3; s++) {
            size_t pa = (size_t)(dir * 3 + s) * NKC + kc;
            rA[s] = reinterpret_cast<const uint4*>(d_ax)[(pa * 16384 + m0) * 2 + tid];
            rB[s] = reinterpret_cast<const uint4*>(d_bw)[(pa * 1024 + n0) * 2 + tid];
        }
    };
    // padded store: row = tid>>1, half = tid&1 -> uint4 index row*3 + half
    auto store_regs = [&](int cb) {
        const int ui = (tid >> 1) * 3 + (tid & 1);
#pragma unroll
        for (int s = 0; s < 3; s++) {
            reinterpret_cast<uint4*>(ABUF(sm, cb, s))[ui] = rA[s];
            reinterpret_cast<uint4*>(BBUF(sm, cb, s))[ui] = rB[s];
        }
    };

    load_regs(0);
    store_regs(0);
    __syncthreads();

    for (int c = 0; c < NKC; c++) {
        const int cb = c & 1;
        if (c + 1 < NKC) load_regs(c + 1);

        wmma::fragment<wmma::matrix_a, 16, 16, 16, __nv_bfloat16, wmma::row_major> af[4];
        wmma::fragment<wmma::matrix_b, 16, 16, 16, __nv_bfloat16, wmma::col_major> bfr[2];
#pragma unroll
        for (int pa = 0; pa < 3; pa++) {
            const __nv_bfloat16* Ab = ABUF(sm, cb, pa);
#pragma unroll
            for (int i = 0; i < 4; i++)
                wmma::load_matrix_sync(af[i], Ab + (warp_m + i * 16) * 24, 24);
            const int npb = (pa == 0) ? 3 : (pa == 1) ? 2 : 1;
#pragma unroll
            for (int pb = 0; pb < 3; pb++) {
                if (pb >= npb) break;
                const __nv_bfloat16* Bb = BBUF(sm, cb, pb);
#pragma unroll
                for (int jj = 0; jj < 2; jj++)
                    wmma::load_matrix_sync(bfr[jj], Bb + (warp_n + jj * 16) * 24, 24);
#pragma unroll
                for (int i = 0; i < 4; i++)
#pragma unroll
                    for (int jj = 0; jj < 2; jj++)
                        wmma::mma_sync(ac[i][jj], af[i], bfr[jj], ac[i][jj]);
            }
        }
        __syncthreads();
        if (c + 1 < NKC) {
            store_regs((c + 1) & 1);
            __syncthreads();
        }
    }

    float* dstbase = d_pre + ((size_t)dir * 16384 + m0) * GG + n0;
#pragma unroll
    for (int i = 0; i < 4; i++)
#pragma unroll
        for (int jj = 0; jj < 2; jj++)
            wmma::store_matrix_sync(
                dstbase + (size_t)(warp_m + i * 16) * GG + warp_n + jj * 16,
                ac[i][jj], GG, wmma::mem_row_major);

    __syncthreads();
    if (tid == 0) {
        unsigned* pc = &d_pcnt[dir * 128 + tg];
        asm volatile("red.release.gpu.global.add.u32 [%0],%1;" :: "l"(pc), "r"(1u) : "memory");
    }
}

// ---------------- LSTM role: persistent recurrence block ------------------
struct LstmS {
    float h_s[2][HH][4];
    float pre_s[2][512];
};

__device__ void lstm_role(int bid, LstmS& S,
    const float* __restrict__ Whf, const float* __restrict__ Whb,
    const float* __restrict__ bf_, const float* __restrict__ bb_)
{
    const int g = bid >> 3;
    const int jc = bid & 7;
    const int dir = g >> 3;
    const int bg = g & 7;
    const float* __restrict__ Whh = dir ? Whb : Whf;
    const float* __restrict__ bias = dir ? bb_ : bf_;
    const int tid = threadIdx.x;
    const int jj = tid >> 3;
    const int kc = tid & 7;
    const int j = jc * 32 + jj;
    unsigned* cnt = &d_cnt[g * 32];

    float w[4][32];
#pragma unroll
    for (int gg = 0; gg < 4; gg++)
#pragma unroll
        for (int kk = 0; kk < 32; kk++)
            w[gg][kk] = __ldg(&Whh[(size_t)(gg * HH + j) * HH + (kk * 8 + kc)]);

    const float bv0 = __ldg(&bias[(tid >> 7) * HH + jc * 32 + (tid & 31)]);
    const float bv1 = __ldg(&bias[((tid >> 7) + 2) * HH + jc * 32 + (tid & 31)]);

    float cst[4] = {0.f, 0.f, 0.f, 0.f};

    if (kc == 0) {
#pragma unroll
        for (int b = 0; b < 4; b++)
            __stcg(&d_hbuf[((0 * 2 + dir) * BB + bg * 4 + b) * HH + j], 0.f);
    }
    __syncthreads();
    if (tid == 0)
        asm volatile("red.release.gpu.global.add.u32 [%0],%1;" :: "l"(cnt), "r"(1u) : "memory");

    for (int t = 0; t < TT; t++) {
        const int par = t & 1;
        if (tid == 0) {
            unsigned v;
            if ((t & 3) == 0) {
                unsigned* pc = &d_pcnt[dir * 128 + (t >> 2)];
                do {
                    asm volatile("ld.acquire.gpu.global.u32 %0,[%1];" : "=r"(v) : "l"(pc));
                } while (v < 8u);
            }
            const unsigned target = 8u * (unsigned)(t + 1);
            do {
                asm volatile("ld.acquire.gpu.global.u32 %0,[%1];" : "=r"(v) : "l"(cnt));
            } while (v < target);
        }
        __syncthreads();

        float pv0, pv1, hv[4];
        {
            size_t pbase = (((size_t)dir * TT + t) * BB + bg * 4) * GG;
            int i0 = tid, i1 = tid + 256;
            pv0 = __ldcg(&d_pre[pbase + (size_t)((i0 >> 5) & 3) * GG + (i0 >> 7) * HH + jc * 32 + (i0 & 31)]) + bv0;
            pv1 = __ldcg(&d_pre[pbase + (size_t)((i1 >> 5) & 3) * GG + (i1 >> 7) * HH + jc * 32 + (i1 & 31)]) + bv1;
        }
#pragma unroll
        for (int q = 0; q < 4; q++) {
            int i = tid + q * 256;
            int b = i >> 8, k = i & 255;
            hv[q] = __ldcg(&d_hbuf[((par * 2 + dir) * BB + bg * 4 + b) * HH + k]);
        }
        S.pre_s[par][tid] = pv0;
        S.pre_s[par][tid + 256] = pv1;
#pragma unroll
        for (int q = 0; q < 4; q++) {
            int i = tid + q * 256;
            S.h_s[par][i & 255][i >> 8] = hv[q];
        }
        __syncthreads();

        ull acc[4][2];
#pragma unroll
        for (int gg = 0; gg < 4; gg++) { acc[gg][0] = 0ull; acc[gg][1] = 0ull; }
#pragma unroll
        for (int kk = 0; kk < 32; kk++) {
            int k = kk * 8 + kc;
            ull hp0 = *reinterpret_cast<const ull*>(&S.h_s[par][k][0]);
            ull hp1 = *reinterpret_cast<const ull*>(&S.h_s[par][k][2]);
#pragma unroll
            for (int gg = 0; gg < 4; gg++) {
                ull wd = pack2(w[gg][kk], w[gg][kk]);
                acc[gg][0] = ffma2(wd, hp0, acc[gg][0]);
                acc[gg][1] = ffma2(wd, hp1, acc[gg][1]);
            }
        }
        float s[4][4];
#pragma unroll
        for (int gg = 0; gg < 4; gg++) {
            unpack2(acc[gg][0], s[gg][0], s[gg][1]);
            unpack2(acc[gg][1], s[gg][2], s[gg][3]);
        }
#pragma unroll
        for (int d = 1; d < 8; d <<= 1)
#pragma unroll
            for (int gg = 0; gg < 4; gg++)
#pragma unroll
                for (int b = 0; b < 4; b++)
                    s[gg][b] += __shfl_xor_sync(0xffffffffu, s[gg][b], d);

        if (kc == 0) {
#pragma unroll
            for (int b = 0; b < 4; b++) {
                float gi = s[0][b] + S.pre_s[par][0 * 128 + b * 32 + jj];
                float gf = s[1][b] + S.pre_s[par][1 * 128 + b * 32 + jj];
                float gg2 = s[2][b] + S.pre_s[par][2 * 128 + b * 32 + jj];
                float go = s[3][b] + S.pre_s[par][3 * 128 + b * 32 + jj];
                float c = sigmoidf_(gf) * cst[b] + sigmoidf_(gi) * tanhf(gg2);
                cst[b] = c;
                float h = sigmoidf_(go) * tanhf(c);
                int gb = bg * 4 + b;
                __stcg(&d_hbuf[(((par ^ 1) * 2 + dir) * BB + gb) * HH + j], h);
                d_hall[(((size_t)dir * TT + t) * BB + gb) * HH + j] = h;
            }
        }
        __syncthreads();
        if (tid == 0)
            asm volatile("red.release.gpu.global.add.u32 [%0],%1;" :: "l"(cnt), "r"(1u) : "memory");
    }
}

// ============ K1: fused wmma-GEMM + LSTM =============
__global__ void __launch_bounds__(256, 2) k_fused(
    const float* __restrict__ Whf, const float* __restrict__ Whb,
    const float* __restrict__ bf_, const float* __restrict__ bb_)
{
    extern __shared__ __align__(256) char sm[];
    if (blockIdx.x < 128) {
        lstm_role(blockIdx.x, *reinterpret_cast<LstmS*>(sm), Whf, Whb, bf_, bb_);
    } else {
        gemm_role(blockIdx.x - 128, sm);
    }
}

// ============ K3: emissions — 256 blocks of 64 timesteps ==================
__global__ void __launch_bounds__(256) k_emis(
    const int* __restrict__ lengths,
    const float* __restrict__ Wclf, const float* __restrict__ bclf)
{
    const int b = blockIdx.x;
    const int tc = blockIdx.y;
    const int tid = threadIdx.x;
    const int k = tid >> 3;
    const int c8 = tid & 7;
    const int L = __ldg(&lengths[b]);

    ull wreg[32];
#pragma unroll
    for (int q = 0; q < 32; q++) {
        int p = q * 8 + c8;
        wreg[q] = pack2(__ldg(&Wclf[(size_t)k * 512 + 2 * p]),
                        __ldg(&Wclf[(size_t)k * 512 + 2 * p + 1]));
    }
    const float bias = __ldg(&bclf[k]);

    __shared__ float hs[2][512];

    auto load_row = [&](int t, float& v0, float& v1) {
        v0 = d_hall[(((size_t)0 * TT + t) * BB + b) * HH + tid];
        int st = (t < L) ? (L - 1 - t) : t;
        v1 = d_hall[(((size_t)1 * TT + st) * BB + b) * HH + tid];
    };

    float v0, v1;
    load_row(tc * 64, v0, v1);
    for (int tt = 0; tt < 64; tt++) {
        const int t = tc * 64 + tt;
        const int par = tt & 1;
        hs[par][tid] = v0;
        hs[par][tid + 256] = v1;
        __syncthreads();
        if (tt + 1 < 64) load_row(t + 1, v0, v1);

        ull acc = 0ull;
#pragma unroll
        for (int q = 0; q < 32; q++) {
            int p = q * 8 + c8;
            acc = ffma2(wreg[q], *reinterpret_cast<const ull*>(&hs[par][2 * p]), acc);
        }
        float lo, hi;
        unpack2(acc, lo, hi);
        float tot = lo + hi;
#pragma unroll
        for (int d = 1; d < 8; d <<= 1)
            tot += __shfl_xor_sync(0xffffffffu, tot, d);
        if (c8 == 0)
            d_em[((size_t)b * TT + t) * KK + k] = tot + bias;
    }
}

// ---------------- warp float max via REDUX ----------------
__device__ __forceinline__ float warp_max32(float x) {
    int k = __float_as_int(x);
    k = (k >= 0) ? k : (k ^ 0x7fffffff);
    int m = __reduce_max_sync(0xffffffffu, k);
    m = (m >= 0) ? m : (m ^ 0x7fffffff);
    return __int_as_float(m);
}

// ============ K4: CRF forward + Viterbi, 2 warps per batch ================
__global__ void __launch_bounds__(64) k_crf(
    const int* __restrict__ lengths, const int* __restrict__ targets,
    const float* __restrict__ st, const float* __restrict__ en,
    const float* __restrict__ trans)
{
    const int b = blockIdx.x;
    const int wid = threadIdx.x >> 5;
    const int j = threadIdx.x & 31;
    const int L = __ldg(&lengths[b]);
    float e0 = __ldg(&d_em[((size_t)b * TT + 0) * KK + j]);

    if (wid == 0) {
        float etr[32];
#pragma unroll
        for (int i = 0; i < 32; i++) etr[i] = __expf(__ldg(&trans[i * 32 + j]));
        float alpha = __ldg(&st[j]) + e0;
        float e = (L > 1) ? __ldg(&d_em[((size_t)b * TT + 1) * KK + j]) : 0.f;
        for (int t = 1; t < L; t++) {
            float e_cur = e;
            if (t + 1 < L) e = __ldg(&d_em[((size_t)b * TT + t + 1) * KK + j]);
            float m = warp_max32(alpha);
            float ea = __expf(alpha - m);
            float s0 = 0.f, s1 = 0.f, s2 = 0.f, s3 = 0.f;
#pragma unroll
            for (int i = 0; i < 32; i += 4) {
                s0 = fmaf(__shfl_sync(0xffffffffu, ea, i + 0), etr[i + 0], s0);
                s1 = fmaf(__shfl_sync(0xffffffffu, ea, i + 1), etr[i + 1], s1);
                s2 = fmaf(__shfl_sync(0xffffffffu, ea, i + 2), etr[i + 2], s2);
                s3 = fmaf(__shfl_sync(0xffffffffu, ea, i + 3), etr[i + 3], s3);
            }
            alpha = m + __logf((s0 + s1) + (s2 + s3)) + e_cur;
        }
        float a = alpha + __ldg(&en[j]);
        float m2 = warp_max32(a);
        float ssum2 = __expf(a - m2);
#pragma unroll
        for (int o = 16; o; o >>= 1) ssum2 += __shfl_xor_sync(0xffffffffu, ssum2, o);
        float logZ = m2 + __logf(ssum2);
        float np = 0.f;
        for (int t = 1 + j; t < L; t += 32) {
            int pt = __ldg(&targets[b * TT + t - 1]);
            int ct = __ldg(&targets[b * TT + t]);
            np += __ldg(&trans[pt * 32 + ct]) + __ldg(&d_em[((size_t)b * TT + t) * KK + ct]);
        }
#pragma unroll
        for (int o = 16; o; o >>= 1) np += __shfl_xor_sync(0xffffffffu, np, o);
        if (j == 0) {
            int tg0 = __ldg(&targets[b * TT + 0]);
            int tgl = __ldg(&targets[b * TT + L - 1]);
            float num = __ldg(&st[tg0]) + __ldg(&d_em[((size_t)b * TT) * KK + tg0]) + np + __ldg(&en[tgl]);
            d_nll[b] = num - logZ;
        }
    } else {
        float trj[32];
#pragma unroll
        for (int i = 0; i < 32; i++) trj[i] = __ldg(&trans[i * 32 + j]);
        float sc = __ldg(&st[j]) + e0;
        float e = (L > 1) ? __ldg(&d_em[((size_t)b * TT + 1) * KK + j]) : 0.f;
        for (int t = 1; t < L; t++) {
            float e_cur = e;
            if (t + 1 < L) e = __ldg(&d_em[((size_t)b * TT + t + 1) * KK + j]);
            float bm = -1e30f;
            int bi = 0;
#pragma unroll
            for (int i = 0; i < 32; i++) {
                float v = __shfl_sync(0xffffffffu, sc, i) + trj[i];
                bi = (v > bm) ? i : bi;
                bm = fmaxf(bm, v);
            }
            d_hist[((size_t)b * 511 + (t - 1)) * KK + j] = (unsigned char)bi;
            sc = bm + e_cur;
        }
        float bm = sc + __ldg(&en[j]);
        int bi = j;
#pragma unroll
        for (int o = 16; o; o >>= 1) {
            float om = __shfl_xor_sync(0xffffffffu, bm, o);
            int oi = __shfl_xor_sync(0xffffffffu, bi, o);
            if (om > bm || (om == bm && oi < bi)) { bm = om; bi = oi; }
        }
        if (j == 0) d_last[b] = bi;
    }
}

// ============ K5: backtrack + loss =====================
__global__ void __launch_bounds__(128) k_back(
    const int* __restrict__ lengths, float* __restrict__ out, int out_size)
{
    const int b = blockIdx.x;
    const int tid = threadIdx.x;
    const bool has_loss = (out_size >= BB * TT + 1);
    const int off = has_loss ? 1 : 0;
    if (out_size < BB * TT) {
        if (b == 0 && tid == 0 && out_size >= 1) {
            float acc = 0.f;
            for (int q = 0; q < BB; q++) acc += d_nll[q];
            out[0] = -acc / (float)BB;
        }
        return;
    }
    __shared__ __align__(16) unsigned char hist_s[511 * KK];
    __shared__ int path[TT];
    {
        const int4* src = reinterpret_cast<const int4*>(&d_hist[(size_t)b * 511 * KK]);
        int4* dst = reinterpret_cast<int4*>(hist_s);
        for (int i = tid; i < (511 * KK) / 16; i += 128) dst[i] = src[i];
    }
    __syncthreads();
    const int L = lengths[b];
    if (tid == 0) {
        int tag = d_last[b];
        path[TT - 1] = tag;
        for (int s = TT - 2; s >= 0; s--) {
            int t = s + 1;
            int prev = (t < L) ? (int)hist_s[s * KK + tag] : tag;
            path[s] = prev;
            tag = prev;
        }
    }
    __syncthreads();
    for (int s = tid; s < TT; s += 128)
        out[off + b * TT + s] = (s < L) ? (float)path[s] : 0.f;
    if (b == 0 && tid == 0 && has_loss) {
        float acc = 0.f;
        for (int q = 0; q < BB; q++) acc += d_nll[q];
        out[0] = -acc / (float)BB;
    }
}

// ---------------- launch ----------------
extern "C" void kernel_launch(void* const* d_in, const int* in_sizes, int n_in,
                              void* d_out, int out_size)
{
    const float* x      = (const float*)d_in[0];
    const int* lengths  = (const int*)d_in[1];
    const int* targets  = (const int*)d_in[3];
    const float* Wihf   = (const float*)d_in[4];
    const float* Whhf   = (const float*)d_in[5];
    const float* bf_    = (const float*)d_in[6];
    const float* Wihb   = (const float*)d_in[7];
    const float* Whhb   = (const float*)d_in[8];
    const float* bb_    = (const float*)d_in[9];
    const float* Wclf   = (const float*)d_in[10];
    const float* bclf   = (const float*)d_in[11];
    const float* st     = (const float*)d_in[12];
    const float* en     = (const float*)d_in[13];
    const float* tr     = (const float*)d_in[14];

    static int smem_set = 0;
    if (!smem_set) {
        cudaFuncSetAttribute(k_fused, cudaFuncAttributeMaxDynamicSharedMemorySize, SM_DYN);
        smem_set = 1;
    }

    k_init<<<1, 256>>>();
    k_split<<<6528, 256>>>(x, lengths, Wihf, Wihb);
    k_dummy<<<1, 32>>>();
    k_fused<<<128 + 2048, 256, SM_DYN>>>(Whhf, Whhb, bf_, bb_);
    k_emis<<<dim3(32, 8), 256>>>(lengths, Wclf, bclf);
    k_crf<<<32, 64>>>(lengths, targets, st, en, tr);
    k_back<<<32, 128>>>(lengths, (float*)d_out, out_size);
}

// round 14
// speedup vs baseline: 2.0962x; 1.1506x over previous
#include <cuda_runtime.h>
#include <cuda_bf16.h>
#include <mma.h>
#include <math.h>

using namespace nvcuda;

#define TT 512
#define BB 32
#define DD 768
#define HH 256
#define GG 1024   // 4*H
#define KK 32
#define NKC 48    // 768/16 k-chunks

typedef unsigned long long ull;

// ---------------- packed f32x2 helpers ----------------
__device__ __forceinline__ ull pack2(float x, float y) {
    ull r; asm("mov.b64 %0,{%1,%2};" : "=l"(r) : "f"(x), "f"(y)); return r;
}
__device__ __forceinline__ void unpack2(ull v, float& x, float& y) {
    asm("mov.b64 {%0,%1},%2;" : "=f"(x), "=f"(y) : "l"(v));
}
__device__ __forceinline__ ull ffma2(ull a, ull b, ull c) {
    ull d; asm("fma.rn.f32x2 %0,%1,%2,%3;" : "=l"(d) : "l"(a), "l"(b), "l"(c)); return d;
}

// ---------------- device scratch ----------------
__device__ float d_pre[(size_t)2 * TT * BB * GG];      // [dir][m][4H]  (m = t*32+b)
__device__ float d_hall[(size_t)2 * TT * BB * HH];
__device__ float d_hbuf[2 * 2 * BB * HH];
__device__ float d_em[(size_t)BB * TT * KK];
__device__ unsigned char d_hist[(size_t)BB * 511 * KK];
__device__ float d_nll[BB];
__device__ int d_last[BB];
__device__ unsigned d_cnt[16 * 32];
// 2-way split bf16 operands: A planes [(dir*2+s)*48+kc][m(16384)][16]
__device__ __nv_bfloat16 d_ax[(size_t)2 * 2 * NKC * 16384 * 16];
__device__ __nv_bfloat16 d_bw[(size_t)2 * 2 * NKC * 1024 * 16];

__device__ __forceinline__ float sigmoidf_(float v) { return 1.f / (1.f + __expf(-v)); }

// ============ K0: reset counters ===========
__global__ void k_init()
{
    int i = threadIdx.x;
    for (int q = i; q < 16 * 32; q += 256) d_cnt[q] = 0;
}

// ============ K0b: split x and W into 2-component bf16 planes =============
__global__ void __launch_bounds__(256) k_split(
    const float* __restrict__ x, const int* __restrict__ lengths,
    const float* __restrict__ Wf, const float* __restrict__ Wb)
{
    const unsigned u = blockIdx.x * 256 + threadIdx.x;
    const unsigned NA = 2u * NKC * 16384;
    const float* src;
    size_t plane_row;
    bool isA;
    unsigned dir, kc;
    if (u < NA) {
        isA = true;
        unsigned m = u & 16383u;
        unsigned q = u >> 14;
        kc = q % NKC; dir = q / NKC;
        int t = m >> 5, b = m & 31;
        int st = t;
        if (dir) { int L = __ldg(&lengths[b]); st = (t < L) ? (L - 1 - t) : t; }
        src = x + ((size_t)b * TT + st) * DD + kc * 16;
        plane_row = m;
    } else {
        isA = false;
        unsigned v = u - NA;
        unsigned n = v & 1023u;
        unsigned q = v >> 10;
        kc = q % NKC; dir = q / NKC;
        const float* W = dir ? Wb : Wf;
        src = W + (size_t)n * DD + kc * 16;
        plane_row = n;
    }
    unsigned hw[8], mw[8];
#pragma unroll
    for (int i = 0; i < 8; i++) {
        unsigned short hh[2], mm2[2];
#pragma unroll
        for (int p = 0; p < 2; p++) {
            float xv = __ldg(&src[i * 2 + p]);
            __nv_bfloat16 bh = __float2bfloat16_rn(xv);
            float r1 = xv - __bfloat162float(bh);
            __nv_bfloat16 bm = __float2bfloat16_rn(r1);
            hh[p] = __bfloat16_as_ushort(bh);
            mm2[p] = __bfloat16_as_ushort(bm);
        }
        hw[i] = (unsigned)hh[0] | ((unsigned)hh[1] << 16);
        mw[i] = (unsigned)mm2[0] | ((unsigned)mm2[1] << 16);
    }
    if (isA) {
#pragma unroll
        for (int s = 0; s < 2; s++) {
            size_t plane = (size_t)(dir * 2 + s) * NKC + kc;
            uint4* dst = reinterpret_cast<uint4*>(d_ax + (plane * 16384 + plane_row) * 16);
            const unsigned* w = (s == 0) ? hw : mw;
            dst[0] = make_uint4(w[0], w[1], w[2], w[3]);
            dst[1] = make_uint4(w[4], w[5], w[6], w[7]);
        }
    } else {
#pragma unroll
        for (int s = 0; s < 2; s++) {
            size_t plane = (size_t)(dir * 2 + s) * NKC + kc;
            uint4* dst = reinterpret_cast<uint4*>(d_bw + (plane * 1024 + plane_row) * 16);
            const unsigned* w = (s == 0) ? hw : mw;
            dst[0] = make_uint4(w[0], w[1], w[2], w[3]);
            dst[1] = make_uint4(w[4], w[5], w[6], w[7]);
        }
    }
}

// ============ K1: standalone wmma GEMM, 64x64 tiles, low regs =============
// smem rows padded to 24 elems (48B) — conflict-free LDSM (verified R12).
__global__ void __launch_bounds__(256, 2) k_gemm()
{
    __shared__ __nv_bfloat16 sA[2][2][64 * 24];
    __shared__ __nv_bfloat16 sB[2][2][64 * 24];

    const int m0  = blockIdx.x * 64;
    const int n0  = blockIdx.y * 64;
    const int dir = blockIdx.z;
    const int tid = threadIdx.x;
    const int wid = tid >> 5;
    const int warp_m = (wid & 3) * 16;   // 0,16,32,48
    const int warp_n = (wid >> 2) * 32;  // 0,32

    const bool isB = tid >= 128;
    const int lt = tid & 127;
    const int row = lt >> 1, half = lt & 1;

    wmma::fragment<wmma::accumulator, 16, 16, 16, float> ac[2];
    wmma::fill_fragment(ac[0], 0.0f);
    wmma::fill_fragment(ac[1], 0.0f);

    uint4 r[2];
    auto load_regs = [&](int kc) {
#pragma unroll
        for (int s = 0; s < 2; s++) {
            size_t plane = (size_t)(dir * 2 + s) * NKC + kc;
            if (!isB)
                r[s] = reinterpret_cast<const uint4*>(d_ax)[(plane * 16384 + m0 + row) * 2 + half];
            else
                r[s] = reinterpret_cast<const uint4*>(d_bw)[(plane * 1024 + n0 + row) * 2 + half];
        }
    };
    auto store_regs = [&](int cb) {
        const int ui = row * 3 + half;
#pragma unroll
        for (int s = 0; s < 2; s++) {
            if (!isB) reinterpret_cast<uint4*>(sA[cb][s])[ui] = r[s];
            else      reinterpret_cast<uint4*>(sB[cb][s])[ui] = r[s];
        }
    };

    load_regs(0);
    store_regs(0);
    __syncthreads();

    for (int c = 0; c < NKC; c++) {
        const int cb = c & 1;
        if (c + 1 < NKC) load_regs(c + 1);

        // terms: (A0,B0), (A0,B1), (A1,B0)
        const int pa_t[3] = {0, 0, 1};
        const int pb_t[3] = {0, 1, 0};
#pragma unroll
        for (int p = 0; p < 3; p++) {
            wmma::fragment<wmma::matrix_a, 16, 16, 16, __nv_bfloat16, wmma::row_major> af;
            wmma::fragment<wmma::matrix_b, 16, 16, 16, __nv_bfloat16, wmma::col_major> bfr;
            wmma::load_matrix_sync(af, sA[cb][pa_t[p]] + warp_m * 24, 24);
            wmma::load_matrix_sync(bfr, sB[cb][pb_t[p]] + warp_n * 24, 24);
            wmma::mma_sync(ac[0], af, bfr, ac[0]);
            wmma::load_matrix_sync(bfr, sB[cb][pb_t[p]] + (warp_n + 16) * 24, 24);
            wmma::mma_sync(ac[1], af, bfr, ac[1]);
        }
        __syncthreads();
        if (c + 1 < NKC) {
            store_regs((c + 1) & 1);
            __syncthreads();
        }
    }

    float* dst = d_pre + ((size_t)dir * 16384 + m0 + warp_m) * GG + n0 + warp_n;
    wmma::store_matrix_sync(dst, ac[0], GG, wmma::mem_row_major);
    wmma::store_matrix_sync(dst + 16, ac[1], GG, wmma::mem_row_major);
}

// ============ K2: LSTM recurrence — standalone, full regs, group counters ==
__global__ void __launch_bounds__(256, 1) k_lstm(
    const float* __restrict__ Whf, const float* __restrict__ Whb,
    const float* __restrict__ bf_, const float* __restrict__ bb_)
{
    const int bid = blockIdx.x;
    const int g = bid >> 3;
    const int jc = bid & 7;
    const int dir = g >> 3;
    const int bg = g & 7;
    const float* __restrict__ Whh = dir ? Whb : Whf;
    const float* __restrict__ bias = dir ? bb_ : bf_;
    const int tid = threadIdx.x;
    const int jj = tid >> 3;
    const int kc = tid & 7;
    const int j = jc * 32 + jj;
    unsigned* cnt = &d_cnt[g * 32];

    float w[4][32];
#pragma unroll
    for (int gg = 0; gg < 4; gg++)
#pragma unroll
        for (int kk = 0; kk < 32; kk++)
            w[gg][kk] = __ldg(&Whh[(size_t)(gg * HH + j) * HH + (kk * 8 + kc)]);

    const float bv0 = __ldg(&bias[(tid >> 7) * HH + jc * 32 + (tid & 31)]);
    const float bv1 = __ldg(&bias[((tid >> 7) + 2) * HH + jc * 32 + (tid & 31)]);

    __shared__ __align__(16) float h_s[2][HH][4];
    __shared__ float pre_s[2][512];

    float cst[4] = {0.f, 0.f, 0.f, 0.f};

    if (kc == 0) {
#pragma unroll
        for (int b = 0; b < 4; b++)
            __stcg(&d_hbuf[((0 * 2 + dir) * BB + bg * 4 + b) * HH + j], 0.f);
    }
    __syncthreads();
    if (tid == 0)
        asm volatile("red.release.gpu.global.add.u32 [%0],%1;" :: "l"(cnt), "r"(1u) : "memory");

    for (int t = 0; t < TT; t++) {
        const int par = t & 1;
        if (tid == 0) {
            const unsigned target = 8u * (unsigned)(t + 1);
            unsigned v;
            do {
                asm volatile("ld.acquire.gpu.global.u32 %0,[%1];" : "=r"(v) : "l"(cnt));
            } while (v < target);
        }
        __syncthreads();

        float pv0, pv1, hv[4];
        {
            size_t pbase = (((size_t)dir * TT + t) * BB + bg * 4) * GG;
            int i0 = tid, i1 = tid + 256;
            pv0 = __ldcg(&d_pre[pbase + (size_t)((i0 >> 5) & 3) * GG + (i0 >> 7) * HH + jc * 32 + (i0 & 31)]) + bv0;
            pv1 = __ldcg(&d_pre[pbase + (size_t)((i1 >> 5) & 3) * GG + (i1 >> 7) * HH + jc * 32 + (i1 & 31)]) + bv1;
        }
#pragma unroll
        for (int q = 0; q < 4; q++) {
            int i = tid + q * 256;
            int b = i >> 8, k = i & 255;
            hv[q] = __ldcg(&d_hbuf[((par * 2 + dir) * BB + bg * 4 + b) * HH + k]);
        }
        pre_s[par][tid] = pv0;
        pre_s[par][tid + 256] = pv1;
#pragma unroll
        for (int q = 0; q < 4; q++) {
            int i = tid + q * 256;
            h_s[par][i & 255][i >> 8] = hv[q];
        }
        __syncthreads();

        ull acc[4][2];
#pragma unroll
        for (int gg = 0; gg < 4; gg++) { acc[gg][0] = 0ull; acc[gg][1] = 0ull; }
#pragma unroll
        for (int kk = 0; kk < 32; kk++) {
            int k = kk * 8 + kc;
            ull hp0 = *reinterpret_cast<const ull*>(&h_s[par][k][0]);
            ull hp1 = *reinterpret_cast<const ull*>(&h_s[par][k][2]);
#pragma unroll
            for (int gg = 0; gg < 4; gg++) {
                ull wd = pack2(w[gg][kk], w[gg][kk]);
                acc[gg][0] = ffma2(wd, hp0, acc[gg][0]);
                acc[gg][1] = ffma2(wd, hp1, acc[gg][1]);
            }
        }
        float s[4][4];
#pragma unroll
        for (int gg = 0; gg < 4; gg++) {
            unpack2(acc[gg][0], s[gg][0], s[gg][1]);
            unpack2(acc[gg][1], s[gg][2], s[gg][3]);
        }
#pragma unroll
        for (int d = 1; d < 8; d <<= 1)
#pragma unroll
            for (int gg = 0; gg < 4; gg++)
#pragma unroll
                for (int b = 0; b < 4; b++)
                    s[gg][b] += __shfl_xor_sync(0xffffffffu, s[gg][b], d);

        if (kc == 0) {
#pragma unroll
            for (int b = 0; b < 4; b++) {
                float gi = s[0][b] + pre_s[par][0 * 128 + b * 32 + jj];
                float gf = s[1][b] + pre_s[par][1 * 128 + b * 32 + jj];
                float gg2 = s[2][b] + pre_s[par][2 * 128 + b * 32 + jj];
                float go = s[3][b] + pre_s[par][3 * 128 + b * 32 + jj];
                float c = sigmoidf_(gf) * cst[b] + sigmoidf_(gi) * tanhf(gg2);
                cst[b] = c;
                float h = sigmoidf_(go) * tanhf(c);
                int gb = bg * 4 + b;
                __stcg(&d_hbuf[(((par ^ 1) * 2 + dir) * BB + gb) * HH + j], h);
                d_hall[(((size_t)dir * TT + t) * BB + gb) * HH + j] = h;
            }
        }
        __syncthreads();
        if (tid == 0)
            asm volatile("red.release.gpu.global.add.u32 [%0],%1;" :: "l"(cnt), "r"(1u) : "memory");
    }
}

// ============ K3: emissions — 256 blocks of 64 timesteps ==================
__global__ void __launch_bounds__(256) k_emis(
    const int* __restrict__ lengths,
    const float* __restrict__ Wclf, const float* __restrict__ bclf)
{
    const int b = blockIdx.x;
    const int tc = blockIdx.y;
    const int tid = threadIdx.x;
    const int k = tid >> 3;
    const int c8 = tid & 7;
    const int L = __ldg(&lengths[b]);

    ull wreg[32];
#pragma unroll
    for (int q = 0; q < 32; q++) {
        int p = q * 8 + c8;
        wreg[q] = pack2(__ldg(&Wclf[(size_t)k * 512 + 2 * p]),
                        __ldg(&Wclf[(size_t)k * 512 + 2 * p + 1]));
    }
    const float bias = __ldg(&bclf[k]);

    __shared__ float hs[2][512];

    auto load_row = [&](int t, float& v0, float& v1) {
        v0 = d_hall[(((size_t)0 * TT + t) * BB + b) * HH + tid];
        int st = (t < L) ? (L - 1 - t) : t;
        v1 = d_hall[(((size_t)1 * TT + st) * BB + b) * HH + tid];
    };

    float v0, v1;
    load_row(tc * 64, v0, v1);
    for (int tt = 0; tt < 64; tt++) {
        const int t = tc * 64 + tt;
        const int par = tt & 1;
        hs[par][tid] = v0;
        hs[par][tid + 256] = v1;
        __syncthreads();
        if (tt + 1 < 64) load_row(t + 1, v0, v1);

        ull acc = 0ull;
#pragma unroll
        for (int q = 0; q < 32; q++) {
            int p = q * 8 + c8;
            acc = ffma2(wreg[q], *reinterpret_cast<const ull*>(&hs[par][2 * p]), acc);
        }
        float lo, hi;
        unpack2(acc, lo, hi);
        float tot = lo + hi;
#pragma unroll
        for (int d = 1; d < 8; d <<= 1)
            tot += __shfl_xor_sync(0xffffffffu, tot, d);
        if (c8 == 0)
            d_em[((size_t)b * TT + t) * KK + k] = tot + bias;
    }
}

// ---------------- warp float max via REDUX ----------------
__device__ __forceinline__ float warp_max32(float x) {
    int k = __float_as_int(x);
    k = (k >= 0) ? k : (k ^ 0x7fffffff);
    int m = __reduce_max_sync(0xffffffffu, k);
    m = (m >= 0) ? m : (m ^ 0x7fffffff);
    return __int_as_float(m);
}

// ============ K4: CRF forward + Viterbi, 2 warps per batch ================
__global__ void __launch_bounds__(64) k_crf(
    const int* __restrict__ lengths, const int* __restrict__ targets,
    const float* __restrict__ st, const float* __restrict__ en,
    const float* __restrict__ trans)
{
    const int b = blockIdx.x;
    const int wid = threadIdx.x >> 5;
    const int j = threadIdx.x & 31;
    const int L = __ldg(&lengths[b]);
    float e0 = __ldg(&d_em[((size_t)b * TT + 0) * KK + j]);

    if (wid == 0) {
        float etr[32];
#pragma unroll
        for (int i = 0; i < 32; i++) etr[i] = __expf(__ldg(&trans[i * 32 + j]));
        float alpha = __ldg(&st[j]) + e0;
        float e = (L > 1) ? __ldg(&d_em[((size_t)b * TT + 1) * KK + j]) : 0.f;
        for (int t = 1; t < L; t++) {
            float e_cur = e;
            if (t + 1 < L) e = __ldg(&d_em[((size_t)b * TT + t + 1) * KK + j]);
            float m = warp_max32(alpha);
            float ea = __expf(alpha - m);
            float s0 = 0.f, s1 = 0.f, s2 = 0.f, s3 = 0.f;
#pragma unroll
            for (int i = 0; i < 32; i += 4) {
                s0 = fmaf(__shfl_sync(0xffffffffu, ea, i + 0), etr[i + 0], s0);
                s1 = fmaf(__shfl_sync(0xffffffffu, ea, i + 1), etr[i + 1], s1);
                s2 = fmaf(__shfl_sync(0xffffffffu, ea, i + 2), etr[i + 2], s2);
                s3 = fmaf(__shfl_sync(0xffffffffu, ea, i + 3), etr[i + 3], s3);
            }
            alpha = m + __logf((s0 + s1) + (s2 + s3)) + e_cur;
        }
        float a = alpha + __ldg(&en[j]);
        float m2 = warp_max32(a);
        float ssum2 = __expf(a - m2);
#pragma unroll
        for (int o = 16; o; o >>= 1) ssum2 += __shfl_xor_sync(0xffffffffu, ssum2, o);
        float logZ = m2 + __logf(ssum2);
        float np = 0.f;
        for (int t = 1 + j; t < L; t += 32) {
            int pt = __ldg(&targets[b * TT + t - 1]);
            int ct = __ldg(&targets[b * TT + t]);
            np += __ldg(&trans[pt * 32 + ct]) + __ldg(&d_em[((size_t)b * TT + t) * KK + ct]);
        }
#pragma unroll
        for (int o = 16; o; o >>= 1) np += __shfl_xor_sync(0xffffffffu, np, o);
        if (j == 0) {
            int tg0 = __ldg(&targets[b * TT + 0]);
            int tgl = __ldg(&targets[b * TT + L - 1]);
            float num = __ldg(&st[tg0]) + __ldg(&d_em[((size_t)b * TT) * KK + tg0]) + np + __ldg(&en[tgl]);
            d_nll[b] = num - logZ;
        }
    } else {
        float trj[32];
#pragma unroll
        for (int i = 0; i < 32; i++) trj[i] = __ldg(&trans[i * 32 + j]);
        float sc = __ldg(&st[j]) + e0;
        float e = (L > 1) ? __ldg(&d_em[((size_t)b * TT + 1) * KK + j]) : 0.f;
        for (int t = 1; t < L; t++) {
            float e_cur = e;
            if (t + 1 < L) e = __ldg(&d_em[((size_t)b * TT + t + 1) * KK + j]);
            float bm = -1e30f;
            int bi = 0;
#pragma unroll
            for (int i = 0; i < 32; i++) {
                float v = __shfl_sync(0xffffffffu, sc, i) + trj[i];
                bi = (v > bm) ? i : bi;
                bm = fmaxf(bm, v);
            }
            d_hist[((size_t)b * 511 + (t - 1)) * KK + j] = (unsigned char)bi;
            sc = bm + e_cur;
        }
        float bm = sc + __ldg(&en[j]);
        int bi = j;
#pragma unroll
        for (int o = 16; o; o >>= 1) {
            float om = __shfl_xor_sync(0xffffffffu, bm, o);
            int oi = __shfl_xor_sync(0xffffffffu, bi, o);
            if (om > bm || (om == bm && oi < bi)) { bm = om; bi = oi; }
        }
        if (j == 0) d_last[b] = bi;
    }
}

// ============ K5: backtrack + loss =====================
__global__ void __launch_bounds__(128) k_back(
    const int* __restrict__ lengths, float* __restrict__ out, int out_size)
{
    const int b = blockIdx.x;
    const int tid = threadIdx.x;
    const bool has_loss = (out_size >= BB * TT + 1);
    const int off = has_loss ? 1 : 0;
    if (out_size < BB * TT) {
        if (b == 0 && tid == 0 && out_size >= 1) {
            float acc = 0.f;
            for (int q = 0; q < BB; q++) acc += d_nll[q];
            out[0] = -acc / (float)BB;
        }
        return;
    }
    __shared__ __align__(16) unsigned char hist_s[511 * KK];
    __shared__ int path[TT];
    {
        const int4* src = reinterpret_cast<const int4*>(&d_hist[(size_t)b * 511 * KK]);
        int4* dst = reinterpret_cast<int4*>(hist_s);
        for (int i = tid; i < (511 * KK) / 16; i += 128) dst[i] = src[i];
    }
    __syncthreads();
    const int L = lengths[b];
    if (tid == 0) {
        int tag = d_last[b];
        path[TT - 1] = tag;
        for (int s = TT - 2; s >= 0; s--) {
            int t = s + 1;
            int prev = (t < L) ? (int)hist_s[s * KK + tag] : tag;
            path[s] = prev;
            tag = prev;
        }
    }
    __syncthreads();
    for (int s = tid; s < TT; s += 128)
        out[off + b * TT + s] = (s < L) ? (float)path[s] : 0.f;
    if (b == 0 && tid == 0 && has_loss) {
        float acc = 0.f;
        for (int q = 0; q < BB; q++) acc += d_nll[q];
        out[0] = -acc / (float)BB;
    }
}

// ---------------- launch ----------------
extern "C" void kernel_launch(void* const* d_in, const int* in_sizes, int n_in,
                              void* d_out, int out_size)
{
    const float* x      = (const float*)d_in[0];
    const int* lengths  = (const int*)d_in[1];
    const int* targets  = (const int*)d_in[3];
    const float* Wihf   = (const float*)d_in[4];
    const float* Whhf   = (const float*)d_in[5];
    const float* bf_    = (const float*)d_in[6];
    const float* Wihb   = (const float*)d_in[7];
    const float* Whhb   = (const float*)d_in[8];
    const float* bb_    = (const float*)d_in[9];
    const float* Wclf   = (const float*)d_in[10];
    const float* bclf   = (const float*)d_in[11];
    const float* st     = (const float*)d_in[12];
    const float* en     = (const float*)d_in[13];
    const float* tr     = (const float*)d_in[14];

    k_init<<<1, 256>>>();
    k_split<<<6528, 256>>>(x, lengths, Wihf, Wihb);
    k_gemm<<<dim3(256, 16, 2), 256>>>();
    k_lstm<<<128, 256>>>(Whhf, Whhb, bf_, bb_);
    k_emis<<<dim3(32, 8), 256>>>(lengths, Wclf, bclf);
    k_crf<<<32, 64>>>(lengths, targets, st, en, tr);
    k_back<<<32, 128>>>(lengths, (float*)d_out, out_size);
}